// round 1
// baseline (speedup 1.0000x reference)
#include <cuda_runtime.h>
#include <math.h>

// ---------------- problem dims ----------------
#define TOK   4096          // b*l = 2*2048
#define SEQL  2048
#define Hh    1024
#define Ee    2048
#define NHh   32
#define Pp    64
#define Nn    128
#define Qq    128
#define Kc    4
#define CONVD 2304          // E + 2*G*N
#define DIN   4384          // 2E + 2GN + NH
#define FFd   4096
#define NCHUNK 32           // b * (l/Q) = 2*16
#define EPS1  1e-6f
#define NEPS  1e-5f

// ---------------- scratch (device globals; no allocation) ----------------
__device__ float g_hnorm [TOK * Hh];
__device__ float g_zx    [TOK * DIN];
__device__ float g_xbc   [TOK * CONVD];
__device__ float g_dt    [TOK * NHh];
__device__ float g_acs   [NCHUNK * NHh * Qq];
__device__ float g_states[NCHUNK * NHh * Pp * Nn];
__device__ float g_prefix[NCHUNK * NHh * Pp * Nn];
__device__ float g_cb    [NCHUNK * Qq * Qq];
__device__ float g_y     [TOK * Ee];
__device__ float g_y2    [TOK * Ee];
__device__ float g_hid2  [TOK * Hh];
__device__ float g_h2n   [TOK * Hh];
__device__ float g_gate  [TOK * FFd];
__device__ float g_up    [TOK * FFd];

// ---------------- helpers ----------------
__device__ __forceinline__ float block_sum_256(float v) {
    __shared__ float sh[8];
    __syncthreads();
    int lane = threadIdx.x & 31, wid = threadIdx.x >> 5;
#pragma unroll
    for (int o = 16; o > 0; o >>= 1) v += __shfl_down_sync(0xffffffffu, v, o);
    if (lane == 0) sh[wid] = v;
    __syncthreads();
    if (threadIdx.x == 0) {
        float s = 0.f;
#pragma unroll
        for (int i = 0; i < 8; i++) s += sh[i];
        sh[0] = s;
    }
    __syncthreads();
    return sh[0];
}

__device__ __forceinline__ float silu_f(float x) {
    return x / (1.f + expf(-x));
}

// ---------------- rmsnorm ----------------
__global__ void rmsnorm_kernel(const float* __restrict__ x, const float* __restrict__ w,
                               float* __restrict__ out, int cols, float eps) {
    int row = blockIdx.x;
    const float* xr = x + (size_t)row * cols;
    float* orow = out + (size_t)row * cols;
    int per = cols >> 8;              // cols multiple of 256 (1024 or 2048)
    float xv[8];
    float ss = 0.f;
    for (int i = 0; i < per; i++) {
        float v = xr[threadIdx.x + (i << 8)];
        xv[i] = v; ss += v * v;
    }
    float tot = block_sum_256(ss);
    float scale = rsqrtf(tot / (float)cols + eps);
    for (int i = 0; i < per; i++) {
        int c = threadIdx.x + (i << 8);
        orow[c] = xv[i] * scale * w[c];
    }
}

// gated rmsnorm: out = rmsnorm(y * silu(z)) * w ; z = zx[:, :2048]
__global__ void gated_rmsnorm_kernel(const float* __restrict__ y, const float* __restrict__ zx,
                                     const float* __restrict__ w, float* __restrict__ out) {
    int row = blockIdx.x;
    const float* yr = y + (size_t)row * Ee;
    const float* zr = zx + (size_t)row * DIN;
    float* orow = out + (size_t)row * Ee;
    float g[8];
    float ss = 0.f;
#pragma unroll
    for (int i = 0; i < 8; i++) {
        int c = threadIdx.x + (i << 8);
        float z = zr[c];
        float v = yr[c] * silu_f(z);
        g[i] = v; ss += v * v;
    }
    float tot = block_sum_256(ss);
    float scale = rsqrtf(tot / (float)Ee + NEPS);
#pragma unroll
    for (int i = 0; i < 8; i++) {
        int c = threadIdx.x + (i << 8);
        orow[c] = g[i] * scale * w[c];
    }
}

// ---------------- SGEMM: C[M,N] = A[M,K] @ B[N,K]^T (+ addsrc) ----------------
// 128x128 block tile, BK=8, 256 threads, 8x8 per thread.
__global__ __launch_bounds__(256) void sgemm_nt(const float* __restrict__ A,
                                                const float* __restrict__ B,
                                                const float* __restrict__ addsrc,
                                                float* __restrict__ C,
                                                int M, int N, int K) {
    __shared__ float As[8][128];
    __shared__ float Bs[8][128];
    int tid  = threadIdx.x;
    int row0 = blockIdx.y * 128, col0 = blockIdx.x * 128;
    int lrow = tid >> 1, lcol = (tid & 1) << 2;
    const float* Ap = A + (size_t)(row0 + lrow) * K + lcol;
    const float* Bp = B + (size_t)(col0 + lrow) * K + lcol;
    bool bv = (col0 + lrow) < N;
    int ty = tid >> 4, tx = tid & 15;
    float acc[8][8];
#pragma unroll
    for (int i = 0; i < 8; i++)
#pragma unroll
        for (int j = 0; j < 8; j++) acc[i][j] = 0.f;

    for (int k0 = 0; k0 < K; k0 += 8) {
        float4 a4 = *(const float4*)(Ap + k0);
        float4 b4 = bv ? *(const float4*)(Bp + k0) : make_float4(0.f, 0.f, 0.f, 0.f);
        As[lcol + 0][lrow] = a4.x; As[lcol + 1][lrow] = a4.y;
        As[lcol + 2][lrow] = a4.z; As[lcol + 3][lrow] = a4.w;
        Bs[lcol + 0][lrow] = b4.x; Bs[lcol + 1][lrow] = b4.y;
        Bs[lcol + 2][lrow] = b4.z; Bs[lcol + 3][lrow] = b4.w;
        __syncthreads();
#pragma unroll
        for (int kk = 0; kk < 8; kk++) {
            float ra[8], rb[8];
#pragma unroll
            for (int i = 0; i < 8; i++) ra[i] = As[kk][ty * 8 + i];
#pragma unroll
            for (int j = 0; j < 8; j++) rb[j] = Bs[kk][tx * 8 + j];
#pragma unroll
            for (int i = 0; i < 8; i++)
#pragma unroll
                for (int j = 0; j < 8; j++) acc[i][j] += ra[i] * rb[j];
        }
        __syncthreads();
    }
#pragma unroll
    for (int i = 0; i < 8; i++) {
        size_t r = (size_t)(row0 + ty * 8 + i);
#pragma unroll
        for (int j = 0; j < 8; j++) {
            int c = col0 + tx * 8 + j;
            if (c < N) {
                float v = acc[i][j];
                if (addsrc) v += addsrc[r * N + c];
                C[r * N + c] = v;
            }
        }
    }
}

// ---------------- causal depthwise conv (K=4) + bias + silu ----------------
__global__ void conv_silu_kernel(const float* __restrict__ zx,
                                 const float* __restrict__ wc,
                                 const float* __restrict__ bcv,
                                 float* __restrict__ xbc) {
    int idx = blockIdx.x * blockDim.x + threadIdx.x;
    if (idx >= TOK * CONVD) return;
    int t = idx / CONVD, c = idx - t * CONVD;
    int pos = t & (SEQL - 1);
    float s = bcv[c];
#pragma unroll
    for (int k = 0; k < Kc; k++) {
        int sp = pos - (Kc - 1) + k;
        if (sp >= 0)
            s += zx[(size_t)(t - (Kc - 1) + k) * DIN + Ee + c] * wc[c * Kc + k];
    }
    xbc[idx] = silu_f(s);
}

// ---------------- dt = softplus(raw + bias) ----------------
__global__ void dt_kernel(const float* __restrict__ zx, const float* __restrict__ dtb,
                          float* __restrict__ dt) {
    int idx = blockIdx.x * blockDim.x + threadIdx.x;
    if (idx >= TOK * NHh) return;
    int t = idx >> 5, h = idx & 31;
    float x = zx[(size_t)t * DIN + (Ee + CONVD) + h] + dtb[h];
    dt[idx] = (x > 20.f) ? x : log1pf(expf(x));
}

// ---------------- per-chunk cumsum of dA = dt * A ----------------
__global__ void dacs_kernel(const float* __restrict__ dt, const float* __restrict__ alog,
                            float* __restrict__ acs) {
    int bc = blockIdx.x, h = blockIdx.y;
    int tb = ((bc >> 4) << 11) + ((bc & 15) << 7);
    int q = threadIdx.x;
    float a = -expf(alog[h]);
    float v = dt[(tb + q) * NHh + h] * a;
    int lane = q & 31;
#pragma unroll
    for (int o = 1; o < 32; o <<= 1) {
        float n = __shfl_up_sync(0xffffffffu, v, o);
        if (lane >= o) v += n;
    }
    __shared__ float ws[4];
    int wid = q >> 5;
    if (lane == 31) ws[wid] = v;
    __syncthreads();
    float add = 0.f;
    for (int w = 0; w < wid; w++) add += ws[w];
    acs[(bc * NHh + h) * Qq + q] = v + add;
}

// ---------------- per-chunk final states: states[p,n] = sum_q w[q]*x[q,p]*B[q,n] ----------------
__global__ __launch_bounds__(256) void chunk_states_kernel(
    const float* __restrict__ xbc, const float* __restrict__ dt,
    const float* __restrict__ acs, float* __restrict__ states) {
    int bc = blockIdx.x, h = blockIdx.y;
    int tb = ((bc >> 4) << 11) + ((bc & 15) << 7);
    __shared__ float w_s[128];
    __shared__ float xw[32 * 64];
    __shared__ float Bsm[32 * 128];
    int tid = threadIdx.x;
    const float* ac = acs + (bc * NHh + h) * Qq;
    if (tid < 128) {
        float last = ac[127];
        w_s[tid] = __expf(last - ac[tid]) * dt[(tb + tid) * NHh + h];
    }
    __syncthreads();
    int tp = tid >> 4, tn = tid & 15;    // p tile = tp*4 .. +3 ; n tile = tn*8 .. +7
    float acc[4][8] = {};
    for (int qt = 0; qt < 128; qt += 32) {
        for (int i = tid; i < 2048; i += 256) {
            int qq = i >> 6, p = i & 63;
            xw[i] = xbc[(size_t)(tb + qt + qq) * CONVD + h * 64 + p] * w_s[qt + qq];
        }
        for (int i = tid; i < 4096; i += 256) {
            int qq = i >> 7, n = i & 127;
            Bsm[i] = xbc[(size_t)(tb + qt + qq) * CONVD + 2048 + n];
        }
        __syncthreads();
        for (int qq = 0; qq < 32; qq++) {
            float xv[4], bv[8];
#pragma unroll
            for (int i = 0; i < 4; i++) xv[i] = xw[qq * 64 + tp * 4 + i];
#pragma unroll
            for (int j = 0; j < 8; j++) bv[j] = Bsm[qq * 128 + tn * 8 + j];
#pragma unroll
            for (int i = 0; i < 4; i++)
#pragma unroll
                for (int j = 0; j < 8; j++) acc[i][j] += xv[i] * bv[j];
        }
        __syncthreads();
    }
    float* sp = states + (size_t)(bc * NHh + h) * 8192;
#pragma unroll
    for (int i = 0; i < 4; i++)
#pragma unroll
        for (int j = 0; j < 8; j++)
            sp[(tp * 4 + i) * 128 + tn * 8 + j] = acc[i][j];
}

// ---------------- inter-chunk recurrence (16 sequential chunks) ----------------
// prefix[z] = state entering chunk z;  run' = run*exp(A_last[z]) + states[z]
__global__ void chunk_scan_kernel(const float* __restrict__ states,
                                  const float* __restrict__ acs,
                                  float* __restrict__ prefix) {
    int b = blockIdx.x, h = blockIdx.y, tid = threadIdx.x;
    float run[32];
#pragma unroll
    for (int i = 0; i < 32; i++) run[i] = 0.f;
    for (int ch = 0; ch < 16; ch++) {
        int bc = b * 16 + ch;
        size_t base = (size_t)(bc * NHh + h) * 8192;
        float al = expf(acs[(bc * NHh + h) * Qq + 127]);
#pragma unroll
        for (int i = 0; i < 32; i++) {
            int e = (i << 8) + tid;
            prefix[base + e] = run[i];
            run[i] = run[i] * al + states[base + e];
        }
    }
}

// ---------------- CB[q,s] = sum_n C[q,n]*B[s,n] (head-independent, per chunk) ----------------
__global__ __launch_bounds__(256) void cb_kernel(const float* __restrict__ xbc,
                                                 float* __restrict__ cbout) {
    int bc = blockIdx.x;
    int tb = ((bc >> 4) << 11) + ((bc & 15) << 7);
    __shared__ float Ct[128][33];
    __shared__ float Bt[128][33];
    int tid = threadIdx.x;
    int tq = tid >> 4, ts = tid & 15;
    float acc[8][8] = {};
    for (int nt = 0; nt < 128; nt += 32) {
        for (int i = tid; i < 4096; i += 256) {
            int r = i >> 5, nn = i & 31;
            Ct[r][nn] = xbc[(size_t)(tb + r) * CONVD + 2176 + nt + nn];
            Bt[r][nn] = xbc[(size_t)(tb + r) * CONVD + 2048 + nt + nn];
        }
        __syncthreads();
        for (int nn = 0; nn < 32; nn++) {
            float ca[8], bb[8];
#pragma unroll
            for (int i = 0; i < 8; i++) ca[i] = Ct[tq * 8 + i][nn];
#pragma unroll
            for (int j = 0; j < 8; j++) bb[j] = Bt[ts * 8 + j][nn];
#pragma unroll
            for (int i = 0; i < 8; i++)
#pragma unroll
                for (int j = 0; j < 8; j++) acc[i][j] += ca[i] * bb[j];
        }
        __syncthreads();
    }
    float* o = cbout + (size_t)bc * 16384;
#pragma unroll
    for (int i = 0; i < 8; i++)
#pragma unroll
        for (int j = 0; j < 8; j++)
            o[(tq * 8 + i) * 128 + ts * 8 + j] = acc[i][j];
}

// ---------------- Y = diag + off + D*x  per (chunk, head) ----------------
__global__ __launch_bounds__(256) void y_kernel(
    const float* __restrict__ xbc, const float* __restrict__ dt,
    const float* __restrict__ acs, const float* __restrict__ prefix,
    const float* __restrict__ cb, const float* __restrict__ Dw,
    float* __restrict__ y) {
    int bc = blockIdx.x, h = blockIdx.y;
    int tb = ((bc >> 4) << 11) + ((bc & 15) << 7);
    __shared__ float acs_s[128], dts[128];
    __shared__ float pool[6336];
    int tid = threadIdx.x;
    if (tid < 128) {
        acs_s[tid] = acs[(bc * NHh + h) * Qq + tid];
        dts[tid] = dt[(tb + tid) * NHh + h];
    }
    __syncthreads();
    int q = tid >> 1, p0 = (tid & 1) << 5;
    float acc[32];
#pragma unroll
    for (int i = 0; i < 32; i++) acc[i] = 0.f;
    float aq = acs_s[q];

    // phase 1: intra-chunk (diagonal) contribution
    float* xds = pool;              // [32][64]  x * dt
    float* CBs = pool + 2048;       // [128][33]
    const float* cbb = cb + (size_t)bc * 16384;
    for (int st = 0; st < 128; st += 32) {
        for (int i = tid; i < 2048; i += 256) {
            int ss = i >> 6, p = i & 63;
            xds[i] = xbc[(size_t)(tb + st + ss) * CONVD + h * 64 + p] * dts[st + ss];
        }
        for (int i = tid; i < 4096; i += 256) {
            int qq = i >> 5, ss = i & 31;
            CBs[qq * 33 + ss] = cbb[qq * 128 + st + ss];
        }
        __syncthreads();
        int lim = q - st + 1;
        if (lim > 32) lim = 32;
        for (int ss = 0; ss < lim; ss++) {
            float m = CBs[q * 33 + ss] * __expf(aq - acs_s[st + ss]);
            const float* xr = xds + ss * 64 + p0;
#pragma unroll
            for (int i = 0; i < 32; i++) acc[i] += m * xr[i];
        }
        __syncthreads();
    }

    // phase 2: inter-chunk contribution  exp(Acs[q]) * C[q,:] @ prefix[p,:]
    float eq = __expf(aq);
    float* Cs2 = pool;              // [128][33]
    float* prefs = pool + 4224;     // [64][33]
    const float* pref = prefix + (size_t)(bc * NHh + h) * 8192;
    for (int nt = 0; nt < 128; nt += 32) {
        for (int i = tid; i < 4096; i += 256) {
            int qq = i >> 5, nn = i & 31;
            Cs2[qq * 33 + nn] = xbc[(size_t)(tb + qq) * CONVD + 2176 + nt + nn];
        }
        for (int i = tid; i < 2048; i += 256) {
            int p = i >> 5, nn = i & 31;
            prefs[p * 33 + nn] = pref[p * 128 + nt + nn];
        }
        __syncthreads();
        for (int nn = 0; nn < 32; nn++) {
            float cv = Cs2[q * 33 + nn] * eq;
            const float* pr = prefs + p0 * 33 + nn;
#pragma unroll
            for (int i = 0; i < 32; i++) acc[i] += cv * pr[i * 33];
        }
        __syncthreads();
    }

    float Dh = Dw[h];
    int t = tb + q;
    const float* xr = xbc + (size_t)t * CONVD + h * 64 + p0;
    float* yo = y + (size_t)t * Ee + h * 64 + p0;
#pragma unroll
    for (int i = 0; i < 32; i++) yo[i] = acc[i] + Dh * xr[i];
}

// ---------------- silu(g)*u ----------------
__global__ void silu_mul_kernel(const float* __restrict__ g, const float* __restrict__ u,
                                float* __restrict__ o, int n) {
    int i = blockIdx.x * blockDim.x + threadIdx.x;
    if (i < n) {
        float x = g[i];
        o[i] = silu_f(x) * u[i];
    }
}

// ---------------- host launcher ----------------
extern "C" void kernel_launch(void* const* d_in, const int* in_sizes, int n_in,
                              void* d_out, int out_size) {
    const float* hid   = (const float*)d_in[0];
    const float* wln1  = (const float*)d_in[1];
    const float* win   = (const float*)d_in[2];
    const float* wconv = (const float*)d_in[3];
    const float* bconv = (const float*)d_in[4];
    const float* dtb   = (const float*)d_in[5];
    const float* alog  = (const float*)d_in[6];
    const float* Dw    = (const float*)d_in[7];
    const float* wmn   = (const float*)d_in[8];
    const float* wout  = (const float*)d_in[9];
    const float* wln2  = (const float*)d_in[10];
    const float* wg    = (const float*)d_in[11];
    const float* wu    = (const float*)d_in[12];
    const float* wd    = (const float*)d_in[13];
    float* out = (float*)d_out;

    float *hnorm, *zx, *xbc, *dt, *acs, *states, *prefix, *cb, *y, *y2, *hid2, *h2n, *gg, *gu;
    cudaGetSymbolAddress((void**)&hnorm,  g_hnorm);
    cudaGetSymbolAddress((void**)&zx,     g_zx);
    cudaGetSymbolAddress((void**)&xbc,    g_xbc);
    cudaGetSymbolAddress((void**)&dt,     g_dt);
    cudaGetSymbolAddress((void**)&acs,    g_acs);
    cudaGetSymbolAddress((void**)&states, g_states);
    cudaGetSymbolAddress((void**)&prefix, g_prefix);
    cudaGetSymbolAddress((void**)&cb,     g_cb);
    cudaGetSymbolAddress((void**)&y,      g_y);
    cudaGetSymbolAddress((void**)&y2,     g_y2);
    cudaGetSymbolAddress((void**)&hid2,   g_hid2);
    cudaGetSymbolAddress((void**)&h2n,    g_h2n);
    cudaGetSymbolAddress((void**)&gg,     g_gate);
    cudaGetSymbolAddress((void**)&gu,     g_up);

    // 1) pre-norm
    rmsnorm_kernel<<<TOK, 256>>>(hid, wln1, hnorm, Hh, EPS1);
    // 2) in-projection: [4096,1024] @ [4384,1024]^T
    sgemm_nt<<<dim3((DIN + 127) / 128, TOK / 128), 256>>>(hnorm, win, nullptr, zx, TOK, DIN, Hh);
    // 3) causal conv + silu
    conv_silu_kernel<<<(TOK * CONVD + 255) / 256, 256>>>(zx, wconv, bconv, xbc);
    // 4) dt softplus
    dt_kernel<<<(TOK * NHh + 255) / 256, 256>>>(zx, dtb, dt);
    // 5) per-chunk cumsum of dA
    dacs_kernel<<<dim3(NCHUNK, NHh), 128>>>(dt, alog, acs);
    // 6) per-chunk final states
    chunk_states_kernel<<<dim3(NCHUNK, NHh), 256>>>(xbc, dt, acs, states);
    // 7) inter-chunk scan -> entering states
    chunk_scan_kernel<<<dim3(2, NHh), 256>>>(states, acs, prefix);
    // 8) CB per chunk (shared across heads)
    cb_kernel<<<NCHUNK, 256>>>(xbc, cb);
    // 9) Y = diag + off + D*x
    y_kernel<<<dim3(NCHUNK, NHh), 256>>>(xbc, dt, acs, prefix, cb, Dw, y);
    // 10) gated rmsnorm
    gated_rmsnorm_kernel<<<TOK, 256>>>(y, zx, wmn, y2);
    // 11) out-projection + residual add
    sgemm_nt<<<dim3(Hh / 128, TOK / 128), 256>>>(y2, wout, hid, hid2, TOK, Hh, Ee);
    // 12) second norm
    rmsnorm_kernel<<<TOK, 256>>>(hid2, wln2, h2n, Hh, EPS1);
    // 13/14) gate & up projections
    sgemm_nt<<<dim3(FFd / 128, TOK / 128), 256>>>(h2n, wg, nullptr, gg, TOK, FFd, Hh);
    sgemm_nt<<<dim3(FFd / 128, TOK / 128), 256>>>(h2n, wu, nullptr, gu, TOK, FFd, Hh);
    // 15) silu(gate)*up (in place into gg)
    silu_mul_kernel<<<(TOK * FFd + 255) / 256, 256>>>(gg, gu, gg, TOK * FFd);
    // 16) down projection + residual -> output
    sgemm_nt<<<dim3(Hh / 128, TOK / 128), 256>>>(gg, wd, hid2, out, TOK, Hh, FFd);
}

// round 3
// speedup vs baseline: 2.6123x; 2.6123x over previous
#include <cuda_runtime.h>
#include <cstdint>
#include <math.h>

// ---------------- problem dims ----------------
#define TOK   4096
#define SEQL  2048
#define Hh    1024
#define Ee    2048
#define NHh   32
#define Nn    128
#define Qq    128
#define Kc    4
#define CONVD 2304
#define DIN   4384
#define FFd   4096
#define NCHUNK 32
#define EPS1  1e-6f
#define NEPS  1e-5f

// ---------------- scratch ----------------
__device__ float g_hnorm [TOK * Hh];
__device__ float g_zx    [TOK * DIN];
__device__ float g_xbc   [TOK * CONVD];
__device__ float g_dt    [TOK * NHh];
__device__ float g_acs   [NCHUNK * NHh * Qq];
__device__ float g_states[NCHUNK * NHh * 64 * Nn];
__device__ float g_prefix[NCHUNK * NHh * 64 * Nn];
__device__ float g_cb    [NCHUNK * Qq * Qq];
__device__ float g_y     [TOK * Ee];
__device__ float g_y2    [TOK * Ee];
__device__ float g_hid2  [TOK * Hh];
__device__ float g_h2n   [TOK * Hh];
__device__ float g_gate  [TOK * FFd];
__device__ float g_up    [TOK * FFd];
// tf32-rounded weights
__device__ float g_wr_in [DIN * Hh];
__device__ float g_wr_out[Hh * Ee];
__device__ float g_wr_g  [FFd * Hh];
__device__ float g_wr_u  [FFd * Hh];
__device__ float g_wr_d  [Hh * FFd];

// ---------------- helpers ----------------
__device__ __forceinline__ uint32_t smem_u32(const void* p) {
    return (uint32_t)__cvta_generic_to_shared(p);
}
__device__ __forceinline__ float silu_f(float x) { return x / (1.f + expf(-x)); }
__device__ __forceinline__ float rna_tf32(float x) {
    uint32_t r;
    asm("cvt.rna.tf32.f32 %0, %1;" : "=r"(r) : "f"(x));
    return __uint_as_float(r);
}
__device__ __forceinline__ float block_sum_256(float v) {
    __shared__ float sh[8];
    __syncthreads();
    int lane = threadIdx.x & 31, wid = threadIdx.x >> 5;
#pragma unroll
    for (int o = 16; o > 0; o >>= 1) v += __shfl_down_sync(0xffffffffu, v, o);
    if (lane == 0) sh[wid] = v;
    __syncthreads();
    if (threadIdx.x == 0) {
        float s = 0.f;
#pragma unroll
        for (int i = 0; i < 8; i++) s += sh[i];
        sh[0] = s;
    }
    __syncthreads();
    return sh[0];
}

__device__ __forceinline__ void cp_async16(uint32_t dst, const float* src, int sz) {
    asm volatile("cp.async.cg.shared.global [%0], [%1], 16, %2;"
                 :: "r"(dst), "l"((unsigned long long)__cvta_generic_to_global(src)), "r"(sz)
                 : "memory");
}

// ---------------- tf32 mma.sync GEMM: C[M,N] = A[M,K] @ B[N,K]^T (+addsrc) ----------------
// 128x128 CTA tile, BK=32, 4-stage cp.async pipeline, 256 threads (8 warps, 32x64 warp tiles)
#define GSTAGES 4
#define LDST 36                                   // padded row stride (floats)
#define STAGE_FLOATS (2 * 128 * LDST)             // 9216 floats / stage
#define GEMM_DSMEM (GSTAGES * STAGE_FLOATS * 4)   // 147456 bytes

__global__ __launch_bounds__(256) void mma_gemm(
    const float* __restrict__ A, const float* __restrict__ B,
    const float* __restrict__ addsrc, float* __restrict__ C,
    int M, int N, int K)
{
    extern __shared__ float sm[];
    int tid = threadIdx.x;
    int lane = tid & 31, wid = tid >> 5;
    int g = lane >> 2, tg = lane & 3;
    int wm = (wid >> 1) << 5;        // 0,32,64,96
    int wn = (wid & 1) << 6;         // 0,64
    int row0 = blockIdx.y << 7, col0 = blockIdx.x << 7;
    int NC = K >> 5;

    float acc[2][8][4];
#pragma unroll
    for (int i = 0; i < 2; i++)
#pragma unroll
        for (int j = 0; j < 8; j++)
#pragma unroll
            for (int k = 0; k < 4; k++) acc[i][j][k] = 0.f;

    // stage loader
    auto load_stage = [&](int s, int c) {
        float* As = sm + s * STAGE_FLOATS;
        float* Bs = As + 128 * LDST;
        const float* Ag = A + (size_t)row0 * K + (c << 5);
        const float* Bg = B + (size_t)col0 * K + (c << 5);
#pragma unroll
        for (int it = 0; it < 8; it++) {
            int i = tid + (it << 8);
            int isB = i >> 10, j = i & 1023;
            int r = j >> 3, c4 = (j & 7) << 2;
            uint32_t dst = smem_u32((isB ? Bs : As) + r * LDST + c4);
            const float* src = (isB ? Bg : Ag) + (size_t)r * K + c4;
            int sz = (isB && (col0 + r) >= N) ? 0 : 16;
            cp_async16(dst, src, sz);
        }
    };

    // prologue
    for (int s = 0; s < GSTAGES - 1; s++) {
        if (s < NC) load_stage(s, s);
        asm volatile("cp.async.commit_group;" ::: "memory");
    }

    for (int c = 0; c < NC; c++) {
        asm volatile("cp.async.wait_group %0;" :: "n"(GSTAGES - 2) : "memory");
        __syncthreads();
        const float* As = sm + (c % GSTAGES) * STAGE_FLOATS;
        const float* Bs = As + 128 * LDST;
#pragma unroll
        for (int ks = 0; ks < 4; ks++) {
            int k0 = ks << 3;
            uint32_t a[2][4], b[8][2];
#pragma unroll
            for (int mt = 0; mt < 2; mt++) {
                int r = wm + (mt << 4) + g;
                a[mt][0] = __float_as_uint(As[r * LDST + k0 + tg]);
                a[mt][1] = __float_as_uint(As[(r + 8) * LDST + k0 + tg]);
                a[mt][2] = __float_as_uint(As[r * LDST + k0 + tg + 4]);
                a[mt][3] = __float_as_uint(As[(r + 8) * LDST + k0 + tg + 4]);
            }
#pragma unroll
            for (int nt = 0; nt < 8; nt++) {
                int n = wn + (nt << 3) + g;
                b[nt][0] = __float_as_uint(Bs[n * LDST + k0 + tg]);
                b[nt][1] = __float_as_uint(Bs[n * LDST + k0 + tg + 4]);
            }
#pragma unroll
            for (int mt = 0; mt < 2; mt++)
#pragma unroll
                for (int nt = 0; nt < 8; nt++) {
                    asm volatile(
                        "mma.sync.aligned.m16n8k8.row.col.f32.tf32.tf32.f32 "
                        "{%0,%1,%2,%3}, {%4,%5,%6,%7}, {%8,%9}, {%0,%1,%2,%3};"
                        : "+f"(acc[mt][nt][0]), "+f"(acc[mt][nt][1]),
                          "+f"(acc[mt][nt][2]), "+f"(acc[mt][nt][3])
                        : "r"(a[mt][0]), "r"(a[mt][1]), "r"(a[mt][2]), "r"(a[mt][3]),
                          "r"(b[nt][0]), "r"(b[nt][1]));
                }
        }
        int nxt = c + GSTAGES - 1;
        if (nxt < NC) load_stage(nxt % GSTAGES, nxt);
        asm volatile("cp.async.commit_group;" ::: "memory");
    }

    // epilogue
#pragma unroll
    for (int mt = 0; mt < 2; mt++) {
        int r = row0 + wm + (mt << 4) + g;
#pragma unroll
        for (int nt = 0; nt < 8; nt++) {
            int cc = col0 + wn + (nt << 3) + (tg << 1);
            if (cc < N) {
                float v0 = acc[mt][nt][0], v2 = acc[mt][nt][2];
                if (addsrc) {
                    v0 += addsrc[(size_t)r * N + cc];
                    v2 += addsrc[(size_t)(r + 8) * N + cc];
                }
                C[(size_t)r * N + cc] = v0;
                C[(size_t)(r + 8) * N + cc] = v2;
            }
            if (cc + 1 < N) {
                float v1 = acc[mt][nt][1], v3 = acc[mt][nt][3];
                if (addsrc) {
                    v1 += addsrc[(size_t)r * N + cc + 1];
                    v3 += addsrc[(size_t)(r + 8) * N + cc + 1];
                }
                C[(size_t)r * N + cc + 1] = v1;
                C[(size_t)(r + 8) * N + cc + 1] = v3;
            }
        }
    }
}

// ---------------- tf32 round copy ----------------
__global__ void round_tf32_kernel(const float* __restrict__ in, float* __restrict__ out, int n) {
    int i = blockIdx.x * blockDim.x + threadIdx.x;
    if (i < n) out[i] = rna_tf32(in[i]);
}

// ---------------- rmsnorm (tf32-rounded output; feeds GEMM) ----------------
__global__ void rmsnorm_kernel(const float* __restrict__ x, const float* __restrict__ w,
                               float* __restrict__ out, int cols, float eps) {
    int row = blockIdx.x;
    const float* xr = x + (size_t)row * cols;
    float* orow = out + (size_t)row * cols;
    int per = cols >> 8;
    float xv[8];
    float ss = 0.f;
    for (int i = 0; i < per; i++) {
        float v = xr[threadIdx.x + (i << 8)];
        xv[i] = v; ss += v * v;
    }
    float tot = block_sum_256(ss);
    float scale = rsqrtf(tot / (float)cols + eps);
    for (int i = 0; i < per; i++) {
        int c = threadIdx.x + (i << 8);
        orow[c] = rna_tf32(xv[i] * scale * w[c]);
    }
}

// gated rmsnorm (tf32-rounded; feeds out-proj)
__global__ void gated_rmsnorm_kernel(const float* __restrict__ y, const float* __restrict__ zx,
                                     const float* __restrict__ w, float* __restrict__ out) {
    int row = blockIdx.x;
    const float* yr = y + (size_t)row * Ee;
    const float* zr = zx + (size_t)row * DIN;
    float* orow = out + (size_t)row * Ee;
    float g[8];
    float ss = 0.f;
#pragma unroll
    for (int i = 0; i < 8; i++) {
        int c = threadIdx.x + (i << 8);
        float v = yr[c] * silu_f(zr[c]);
        g[i] = v; ss += v * v;
    }
    float tot = block_sum_256(ss);
    float scale = rsqrtf(tot / (float)Ee + NEPS);
#pragma unroll
    for (int i = 0; i < 8; i++) {
        int c = threadIdx.x + (i << 8);
        orow[c] = rna_tf32(g[i] * scale * w[c]);
    }
}

// ---------------- conv + silu ----------------
__global__ void conv_silu_kernel(const float* __restrict__ zx,
                                 const float* __restrict__ wc,
                                 const float* __restrict__ bcv,
                                 float* __restrict__ xbc) {
    int idx = blockIdx.x * blockDim.x + threadIdx.x;
    if (idx >= TOK * CONVD) return;
    int t = idx / CONVD, c = idx - t * CONVD;
    int pos = t & (SEQL - 1);
    float s = bcv[c];
#pragma unroll
    for (int k = 0; k < Kc; k++) {
        int sp = pos - (Kc - 1) + k;
        if (sp >= 0)
            s += zx[(size_t)(t - (Kc - 1) + k) * DIN + Ee + c] * wc[c * Kc + k];
    }
    xbc[idx] = silu_f(s);
}

// ---------------- dt softplus ----------------
__global__ void dt_kernel(const float* __restrict__ zx, const float* __restrict__ dtb,
                          float* __restrict__ dt) {
    int idx = blockIdx.x * blockDim.x + threadIdx.x;
    if (idx >= TOK * NHh) return;
    int t = idx >> 5, h = idx & 31;
    float x = zx[(size_t)t * DIN + (Ee + CONVD) + h] + dtb[h];
    dt[idx] = (x > 20.f) ? x : log1pf(expf(x));
}

// ---------------- per-chunk cumsum of dA ----------------
__global__ void dacs_kernel(const float* __restrict__ dt, const float* __restrict__ alog,
                            float* __restrict__ acs) {
    int bc = blockIdx.x, h = blockIdx.y;
    int tb = ((bc >> 4) << 11) + ((bc & 15) << 7);
    int q = threadIdx.x;
    float a = -expf(alog[h]);
    float v = dt[(tb + q) * NHh + h] * a;
    int lane = q & 31;
#pragma unroll
    for (int o = 1; o < 32; o <<= 1) {
        float n = __shfl_up_sync(0xffffffffu, v, o);
        if (lane >= o) v += n;
    }
    __shared__ float ws[4];
    int wid = q >> 5;
    if (lane == 31) ws[wid] = v;
    __syncthreads();
    float add = 0.f;
    for (int w = 0; w < wid; w++) add += ws[w];
    acs[(bc * NHh + h) * Qq + q] = v + add;
}

// ---------------- per-chunk final states ----------------
__global__ __launch_bounds__(256) void chunk_states_kernel(
    const float* __restrict__ xbc, const float* __restrict__ dt,
    const float* __restrict__ acs, float* __restrict__ states) {
    int bc = blockIdx.x, h = blockIdx.y;
    int tb = ((bc >> 4) << 11) + ((bc & 15) << 7);
    __shared__ float w_s[128];
    __shared__ float xw[32 * 64];
    __shared__ float Bsm[32 * 128];
    int tid = threadIdx.x;
    const float* ac = acs + (bc * NHh + h) * Qq;
    if (tid < 128) {
        float last = ac[127];
        w_s[tid] = __expf(last - ac[tid]) * dt[(tb + tid) * NHh + h];
    }
    __syncthreads();
    int tp = tid >> 4, tn = tid & 15;
    float acc[4][8] = {};
    for (int qt = 0; qt < 128; qt += 32) {
        for (int i = tid; i < 2048; i += 256) {
            int qq = i >> 6, p = i & 63;
            xw[i] = xbc[(size_t)(tb + qt + qq) * CONVD + h * 64 + p] * w_s[qt + qq];
        }
        for (int i = tid; i < 4096; i += 256) {
            int qq = i >> 7, n = i & 127;
            Bsm[i] = xbc[(size_t)(tb + qt + qq) * CONVD + 2048 + n];
        }
        __syncthreads();
        for (int qq = 0; qq < 32; qq++) {
            float xv[4], bv[8];
#pragma unroll
            for (int i = 0; i < 4; i++) xv[i] = xw[qq * 64 + tp * 4 + i];
#pragma unroll
            for (int j = 0; j < 8; j++) bv[j] = Bsm[qq * 128 + tn * 8 + j];
#pragma unroll
            for (int i = 0; i < 4; i++)
#pragma unroll
                for (int j = 0; j < 8; j++) acc[i][j] += xv[i] * bv[j];
        }
        __syncthreads();
    }
    float* sp = states + (size_t)(bc * NHh + h) * 8192;
#pragma unroll
    for (int i = 0; i < 4; i++)
#pragma unroll
        for (int j = 0; j < 8; j++)
            sp[(tp * 4 + i) * 128 + tn * 8 + j] = acc[i][j];
}

// ---------------- inter-chunk recurrence ----------------
__global__ void chunk_scan_kernel(const float* __restrict__ states,
                                  const float* __restrict__ acs,
                                  float* __restrict__ prefix) {
    int b = blockIdx.x, h = blockIdx.y, tid = threadIdx.x;
    float run[32];
#pragma unroll
    for (int i = 0; i < 32; i++) run[i] = 0.f;
    for (int ch = 0; ch < 16; ch++) {
        int bc = b * 16 + ch;
        size_t base = (size_t)(bc * NHh + h) * 8192;
        float al = expf(acs[(bc * NHh + h) * Qq + 127]);
#pragma unroll
        for (int i = 0; i < 32; i++) {
            int e = (i << 8) + tid;
            prefix[base + e] = run[i];
            run[i] = run[i] * al + states[base + e];
        }
    }
}

// ---------------- CB ----------------
__global__ __launch_bounds__(256) void cb_kernel(const float* __restrict__ xbc,
                                                 float* __restrict__ cbout) {
    int bc = blockIdx.x;
    int tb = ((bc >> 4) << 11) + ((bc & 15) << 7);
    __shared__ float Ct[128][33];
    __shared__ float Bt[128][33];
    int tid = threadIdx.x;
    int tq = tid >> 4, ts = tid & 15;
    float acc[8][8] = {};
    for (int nt = 0; nt < 128; nt += 32) {
        for (int i = tid; i < 4096; i += 256) {
            int r = i >> 5, nn = i & 31;
            Ct[r][nn] = xbc[(size_t)(tb + r) * CONVD + 2176 + nt + nn];
            Bt[r][nn] = xbc[(size_t)(tb + r) * CONVD + 2048 + nt + nn];
        }
        __syncthreads();
        for (int nn = 0; nn < 32; nn++) {
            float ca[8], bb[8];
#pragma unroll
            for (int i = 0; i < 8; i++) ca[i] = Ct[tq * 8 + i][nn];
#pragma unroll
            for (int j = 0; j < 8; j++) bb[j] = Bt[ts * 8 + j][nn];
#pragma unroll
            for (int i = 0; i < 8; i++)
#pragma unroll
                for (int j = 0; j < 8; j++) acc[i][j] += ca[i] * bb[j];
        }
        __syncthreads();
    }
    float* o = cbout + (size_t)bc * 16384;
#pragma unroll
    for (int i = 0; i < 8; i++)
#pragma unroll
        for (int j = 0; j < 8; j++)
            o[(tq * 8 + i) * 128 + ts * 8 + j] = acc[i][j];
}

// ---------------- Y ----------------
__global__ __launch_bounds__(256) void y_kernel(
    const float* __restrict__ xbc, const float* __restrict__ dt,
    const float* __restrict__ acs, const float* __restrict__ prefix,
    const float* __restrict__ cb, const float* __restrict__ Dw,
    float* __restrict__ y) {
    int bc = blockIdx.x, h = blockIdx.y;
    int tb = ((bc >> 4) << 11) + ((bc & 15) << 7);
    __shared__ float acs_s[128], dts[128];
    __shared__ float pool[6336];
    int tid = threadIdx.x;
    if (tid < 128) {
        acs_s[tid] = acs[(bc * NHh + h) * Qq + tid];
        dts[tid] = dt[(tb + tid) * NHh + h];
    }
    __syncthreads();
    int q = tid >> 1, p0 = (tid & 1) << 5;
    float acc[32];
#pragma unroll
    for (int i = 0; i < 32; i++) acc[i] = 0.f;
    float aq = acs_s[q];

    float* xds = pool;
    float* CBs = pool + 2048;
    const float* cbb = cb + (size_t)bc * 16384;
    for (int st = 0; st < 128; st += 32) {
        for (int i = tid; i < 2048; i += 256) {
            int ss = i >> 6, p = i & 63;
            xds[i] = xbc[(size_t)(tb + st + ss) * CONVD + h * 64 + p] * dts[st + ss];
        }
        for (int i = tid; i < 4096; i += 256) {
            int qq = i >> 5, ss = i & 31;
            CBs[qq * 33 + ss] = cbb[qq * 128 + st + ss];
        }
        __syncthreads();
        int lim = q - st + 1;
        if (lim > 32) lim = 32;
        for (int ss = 0; ss < lim; ss++) {
            float m = CBs[q * 33 + ss] * __expf(aq - acs_s[st + ss]);
            const float* xr = xds + ss * 64 + p0;
#pragma unroll
            for (int i = 0; i < 32; i++) acc[i] += m * xr[i];
        }
        __syncthreads();
    }

    float eq = __expf(aq);
    float* Cs2 = pool;
    float* prefs = pool + 4224;
    const float* pref = prefix + (size_t)(bc * NHh + h) * 8192;
    for (int nt = 0; nt < 128; nt += 32) {
        for (int i = tid; i < 4096; i += 256) {
            int qq = i >> 5, nn = i & 31;
            Cs2[qq * 33 + nn] = xbc[(size_t)(tb + qq) * CONVD + 2176 + nt + nn];
        }
        for (int i = tid; i < 2048; i += 256) {
            int p = i >> 5, nn = i & 31;
            prefs[p * 33 + nn] = pref[p * 128 + nt + nn];
        }
        __syncthreads();
        for (int nn = 0; nn < 32; nn++) {
            float cv = Cs2[q * 33 + nn] * eq;
            const float* pr = prefs + p0 * 33 + nn;
#pragma unroll
            for (int i = 0; i < 32; i++) acc[i] += cv * pr[i * 33];
        }
        __syncthreads();
    }

    float Dh = Dw[h];
    int t = tb + q;
    const float* xr = xbc + (size_t)t * CONVD + h * 64 + p0;
    float* yo = y + (size_t)t * Ee + h * 64 + p0;
#pragma unroll
    for (int i = 0; i < 32; i++) yo[i] = acc[i] + Dh * xr[i];
}

// ---------------- silu(g)*u (tf32-rounded; feeds down-proj) ----------------
__global__ void silu_mul_kernel(const float* __restrict__ g, const float* __restrict__ u,
                                float* __restrict__ o, int n) {
    int i = blockIdx.x * blockDim.x + threadIdx.x;
    if (i < n) o[i] = rna_tf32(silu_f(g[i]) * u[i]);
}

// ---------------- host launcher ----------------
extern "C" void kernel_launch(void* const* d_in, const int* in_sizes, int n_in,
                              void* d_out, int out_size) {
    const float* hid   = (const float*)d_in[0];
    const float* wln1  = (const float*)d_in[1];
    const float* win   = (const float*)d_in[2];
    const float* wconv = (const float*)d_in[3];
    const float* bconv = (const float*)d_in[4];
    const float* dtb   = (const float*)d_in[5];
    const float* alog  = (const float*)d_in[6];
    const float* Dw    = (const float*)d_in[7];
    const float* wmn   = (const float*)d_in[8];
    const float* wout  = (const float*)d_in[9];
    const float* wln2  = (const float*)d_in[10];
    const float* wg    = (const float*)d_in[11];
    const float* wu    = (const float*)d_in[12];
    const float* wd    = (const float*)d_in[13];
    float* out = (float*)d_out;

    float *hnorm, *zx, *xbc, *dt, *acs, *states, *prefix, *cbp, *y, *y2, *hid2, *h2n, *gg, *gu;
    float *wr_in, *wr_out, *wr_g, *wr_u, *wr_d;
    cudaGetSymbolAddress((void**)&hnorm,  g_hnorm);
    cudaGetSymbolAddress((void**)&zx,     g_zx);
    cudaGetSymbolAddress((void**)&xbc,    g_xbc);
    cudaGetSymbolAddress((void**)&dt,     g_dt);
    cudaGetSymbolAddress((void**)&acs,    g_acs);
    cudaGetSymbolAddress((void**)&states, g_states);
    cudaGetSymbolAddress((void**)&prefix, g_prefix);
    cudaGetSymbolAddress((void**)&cbp,    g_cb);
    cudaGetSymbolAddress((void**)&y,      g_y);
    cudaGetSymbolAddress((void**)&y2,     g_y2);
    cudaGetSymbolAddress((void**)&hid2,   g_hid2);
    cudaGetSymbolAddress((void**)&h2n,    g_h2n);
    cudaGetSymbolAddress((void**)&gg,     g_gate);
    cudaGetSymbolAddress((void**)&gu,     g_up);
    cudaGetSymbolAddress((void**)&wr_in,  g_wr_in);
    cudaGetSymbolAddress((void**)&wr_out, g_wr_out);
    cudaGetSymbolAddress((void**)&wr_g,   g_wr_g);
    cudaGetSymbolAddress((void**)&wr_u,   g_wr_u);
    cudaGetSymbolAddress((void**)&wr_d,   g_wr_d);

    cudaFuncSetAttribute(mma_gemm, cudaFuncAttributeMaxDynamicSharedMemorySize, GEMM_DSMEM);

    // round weights to tf32 (rna)
    round_tf32_kernel<<<(DIN * Hh + 255) / 256, 256>>>(win,  wr_in,  DIN * Hh);
    round_tf32_kernel<<<(Hh * Ee + 255) / 256, 256>>>(wout, wr_out, Hh * Ee);
    round_tf32_kernel<<<(FFd * Hh + 255) / 256, 256>>>(wg,   wr_g,   FFd * Hh);
    round_tf32_kernel<<<(FFd * Hh + 255) / 256, 256>>>(wu,   wr_u,   FFd * Hh);
    round_tf32_kernel<<<(Hh * FFd + 255) / 256, 256>>>(wd,   wr_d,   Hh * FFd);

    // 1) pre-norm
    rmsnorm_kernel<<<TOK, 256>>>(hid, wln1, hnorm, Hh, EPS1);
    // 2) in-projection
    mma_gemm<<<dim3((DIN + 127) / 128, TOK / 128), 256, GEMM_DSMEM>>>(hnorm, wr_in, nullptr, zx, TOK, DIN, Hh);
    // 3) conv + silu
    conv_silu_kernel<<<(TOK * CONVD + 255) / 256, 256>>>(zx, wconv, bconv, xbc);
    // 4) dt
    dt_kernel<<<(TOK * NHh + 255) / 256, 256>>>(zx, dtb, dt);
    // 5) cumsum
    dacs_kernel<<<dim3(NCHUNK, NHh), 128>>>(dt, alog, acs);
    // 6) chunk states
    chunk_states_kernel<<<dim3(NCHUNK, NHh), 256>>>(xbc, dt, acs, states);
    // 7) scan
    chunk_scan_kernel<<<dim3(2, NHh), 256>>>(states, acs, prefix);
    // 8) CB
    cb_kernel<<<NCHUNK, 256>>>(xbc, cbp);
    // 9) Y
    y_kernel<<<dim3(NCHUNK, NHh), 256>>>(xbc, dt, acs, prefix, cbp, Dw, y);
    // 10) gated norm
    gated_rmsnorm_kernel<<<TOK, 256>>>(y, zx, wmn, y2);
    // 11) out-proj + residual
    mma_gemm<<<dim3(Hh / 128, TOK / 128), 256, GEMM_DSMEM>>>(y2, wr_out, hid, hid2, TOK, Hh, Ee);
    // 12) norm 2
    rmsnorm_kernel<<<TOK, 256>>>(hid2, wln2, h2n, Hh, EPS1);
    // 13/14) gate & up
    mma_gemm<<<dim3(FFd / 128, TOK / 128), 256, GEMM_DSMEM>>>(h2n, wr_g, nullptr, gg, TOK, FFd, Hh);
    mma_gemm<<<dim3(FFd / 128, TOK / 128), 256, GEMM_DSMEM>>>(h2n, wr_u, nullptr, gu, TOK, FFd, Hh);
    // 15) silu*up
    silu_mul_kernel<<<(TOK * FFd + 255) / 256, 256>>>(gg, gu, gg, TOK * FFd);
    // 16) down + residual
    mma_gemm<<<dim3(Hh / 128, TOK / 128), 256, GEMM_DSMEM>>>(gg, wr_d, hid2, out, TOK, Hh, FFd);
}

// round 4
// speedup vs baseline: 2.6959x; 1.0320x over previous
#include <cuda_runtime.h>
#include <cstdint>
#include <math.h>

// ---------------- problem dims ----------------
#define TOK   4096
#define SEQL  2048
#define Hh    1024
#define Ee    2048
#define NHh   32
#define Nn    128
#define Qq    128
#define Kc    4
#define CONVD 2304
#define DIN   4384
#define FFd   4096
#define NCHUNK 32
#define EPS1  1e-6f
#define NEPS  1e-5f

// ---------------- scratch ----------------
__device__ float g_hnorm [TOK * Hh];
__device__ float g_zx    [TOK * DIN];
__device__ float g_xbc   [TOK * CONVD];
__device__ float g_dt    [TOK * NHh];
__device__ float g_acs   [NCHUNK * NHh * Qq];
__device__ float g_states[NCHUNK * NHh * 64 * Nn];
__device__ float g_prefix[NCHUNK * NHh * 64 * Nn];
__device__ float g_cb    [NCHUNK * Qq * Qq];
__device__ float g_y     [TOK * Ee];
__device__ float g_y2    [TOK * Ee];
__device__ float g_hid2  [TOK * Hh];
__device__ float g_h2n   [TOK * Hh];
__device__ float g_gate  [TOK * FFd];
__device__ float g_up    [TOK * FFd];
// tf32-rounded weights
__device__ float g_wr_in [DIN * Hh];
__device__ float g_wr_out[Hh * Ee];
__device__ float g_wr_g  [FFd * Hh];
__device__ float g_wr_u  [FFd * Hh];
__device__ float g_wr_d  [Hh * FFd];

// ---------------- helpers ----------------
__device__ __forceinline__ uint32_t smem_u32(const void* p) {
    return (uint32_t)__cvta_generic_to_shared(p);
}
__device__ __forceinline__ float silu_f(float x) { return x / (1.f + expf(-x)); }
__device__ __forceinline__ float rna_tf32(float x) {
    uint32_t r;
    asm("cvt.rna.tf32.f32 %0, %1;" : "=r"(r) : "f"(x));
    return __uint_as_float(r);
}
__device__ __forceinline__ float block_sum_256(float v) {
    __shared__ float sh[8];
    __syncthreads();
    int lane = threadIdx.x & 31, wid = threadIdx.x >> 5;
#pragma unroll
    for (int o = 16; o > 0; o >>= 1) v += __shfl_down_sync(0xffffffffu, v, o);
    if (lane == 0) sh[wid] = v;
    __syncthreads();
    if (threadIdx.x == 0) {
        float s = 0.f;
#pragma unroll
        for (int i = 0; i < 8; i++) s += sh[i];
        sh[0] = s;
    }
    __syncthreads();
    return sh[0];
}

__device__ __forceinline__ void cp_async16(uint32_t dst, const float* src, int sz) {
    asm volatile("cp.async.cg.shared.global [%0], [%1], 16, %2;"
                 :: "r"(dst), "l"((unsigned long long)__cvta_generic_to_global(src)), "r"(sz)
                 : "memory");
}

// ---------------- tf32 mma.sync GEMM: C[M,N] = A[M,K] @ B[N,K]^T (+addsrc) ----------------
// 256x128 CTA tile, BK=32, 3-stage cp.async pipeline, 256 threads.
// 8 warps in 4(M) x 2(N) grid -> 64x64 warp tile = 4(mt) x 8(nt) m16n8k8 MMAs.
// MODE: 0 = plain store, 1 = add addsrc, 2 = fused silu(gatebuf)*acc (up-proj epilogue)
#define GSTAGES 3
#define LDST 36
#define STAGE_FLOATS (384 * LDST)                  // (256 A rows + 128 B rows) * 36
#define GEMM_DSMEM (GSTAGES * STAGE_FLOATS * 4)    // 165888 bytes

template<int MODE>
__global__ __launch_bounds__(256, 1) void mma_gemm(
    const float* __restrict__ A, const float* __restrict__ B,
    const float* __restrict__ aux, float* __restrict__ C,
    int M, int N, int K)
{
    extern __shared__ float sm[];
    int tid = threadIdx.x;
    int lane = tid & 31, wid = tid >> 5;
    int g = lane >> 2, tg = lane & 3;
    int wm = (wid >> 1) << 6;        // 0,64,128,192
    int wn = (wid & 1) << 6;         // 0,64
    int row0 = blockIdx.y << 8, col0 = blockIdx.x << 7;
    int NC = K >> 5;

    float acc[4][8][4];
#pragma unroll
    for (int i = 0; i < 4; i++)
#pragma unroll
        for (int j = 0; j < 8; j++)
#pragma unroll
            for (int k = 0; k < 4; k++) acc[i][j][k] = 0.f;

    auto load_stage = [&](int s, int c) {
        float* As = sm + s * STAGE_FLOATS;
        float* Bs = As + 256 * LDST;
        const float* Ag = A + (size_t)row0 * K + (c << 5);
        const float* Bg = B + (size_t)col0 * K + (c << 5);
#pragma unroll
        for (int it = 0; it < 12; it++) {
            int i = tid + (it << 8);
            if (i < 2048) {
                int r = i >> 3, c4 = (i & 7) << 2;
                cp_async16(smem_u32(As + r * LDST + c4), Ag + (size_t)r * K + c4, 16);
            } else {
                int j = i - 2048;
                int r = j >> 3, c4 = (j & 7) << 2;
                int sz = (col0 + r < N) ? 16 : 0;
                cp_async16(smem_u32(Bs + r * LDST + c4), Bg + (size_t)r * K + c4, sz);
            }
        }
    };

    // prologue: fill stages 0..GSTAGES-2
#pragma unroll
    for (int s = 0; s < GSTAGES - 1; s++) {
        load_stage(s, s);
        asm volatile("cp.async.commit_group;" ::: "memory");
    }

    for (int c = 0; c < NC; c++) {
        asm volatile("cp.async.wait_group %0;" :: "n"(GSTAGES - 2) : "memory");
        __syncthreads();
        // issue next-stage loads first so they overlap compute
        int nxt = c + GSTAGES - 1;
        if (nxt < NC) load_stage(nxt % GSTAGES, nxt);
        asm volatile("cp.async.commit_group;" ::: "memory");

        const float* As = sm + (c % GSTAGES) * STAGE_FLOATS;
        const float* Bs = As + 256 * LDST;
#pragma unroll
        for (int ks = 0; ks < 4; ks++) {
            int k0 = ks << 3;
            uint32_t a[4][4], b[8][2];
#pragma unroll
            for (int mt = 0; mt < 4; mt++) {
                int r = wm + (mt << 4) + g;
                a[mt][0] = __float_as_uint(As[r * LDST + k0 + tg]);
                a[mt][1] = __float_as_uint(As[(r + 8) * LDST + k0 + tg]);
                a[mt][2] = __float_as_uint(As[r * LDST + k0 + tg + 4]);
                a[mt][3] = __float_as_uint(As[(r + 8) * LDST + k0 + tg + 4]);
            }
#pragma unroll
            for (int nt = 0; nt < 8; nt++) {
                int n = wn + (nt << 3) + g;
                b[nt][0] = __float_as_uint(Bs[n * LDST + k0 + tg]);
                b[nt][1] = __float_as_uint(Bs[n * LDST + k0 + tg + 4]);
            }
#pragma unroll
            for (int mt = 0; mt < 4; mt++)
#pragma unroll
                for (int nt = 0; nt < 8; nt++) {
                    asm volatile(
                        "mma.sync.aligned.m16n8k8.row.col.f32.tf32.tf32.f32 "
                        "{%0,%1,%2,%3}, {%4,%5,%6,%7}, {%8,%9}, {%0,%1,%2,%3};"
                        : "+f"(acc[mt][nt][0]), "+f"(acc[mt][nt][1]),
                          "+f"(acc[mt][nt][2]), "+f"(acc[mt][nt][3])
                        : "r"(a[mt][0]), "r"(a[mt][1]), "r"(a[mt][2]), "r"(a[mt][3]),
                          "r"(b[nt][0]), "r"(b[nt][1]));
                }
        }
    }

    // epilogue (float2 stores; thread owns columns cc, cc+1)
#pragma unroll
    for (int mt = 0; mt < 4; mt++) {
        int r = row0 + wm + (mt << 4) + g;
#pragma unroll
        for (int nt = 0; nt < 8; nt++) {
            int cc = col0 + wn + (nt << 3) + (tg << 1);
            if (cc >= N) continue;
            float v0 = acc[mt][nt][0], v1 = acc[mt][nt][1];
            float v2 = acc[mt][nt][2], v3 = acc[mt][nt][3];
            if (MODE == 1) {
                float2 s0 = *(const float2*)(aux + (size_t)r * N + cc);
                float2 s1 = *(const float2*)(aux + (size_t)(r + 8) * N + cc);
                v0 += s0.x; v1 += s0.y; v2 += s1.x; v3 += s1.y;
            } else if (MODE == 2) {
                float2 g0 = *(const float2*)(aux + (size_t)r * N + cc);
                float2 g1 = *(const float2*)(aux + (size_t)(r + 8) * N + cc);
                v0 = rna_tf32(silu_f(g0.x) * v0);
                v1 = rna_tf32(silu_f(g0.y) * v1);
                v2 = rna_tf32(silu_f(g1.x) * v2);
                v3 = rna_tf32(silu_f(g1.y) * v3);
            }
            *(float2*)(C + (size_t)r * N + cc) = make_float2(v0, v1);
            *(float2*)(C + (size_t)(r + 8) * N + cc) = make_float2(v2, v3);
        }
    }
}

// ---------------- tf32 round copy ----------------
__global__ void round_tf32_kernel(const float* __restrict__ in, float* __restrict__ out, int n) {
    int i = blockIdx.x * blockDim.x + threadIdx.x;
    if (i < n) out[i] = rna_tf32(in[i]);
}

// ---------------- rmsnorm (tf32-rounded output; feeds GEMM) ----------------
__global__ void rmsnorm_kernel(const float* __restrict__ x, const float* __restrict__ w,
                               float* __restrict__ out, int cols, float eps) {
    int row = blockIdx.x;
    const float* xr = x + (size_t)row * cols;
    float* orow = out + (size_t)row * cols;
    int per = cols >> 8;
    float xv[8];
    float ss = 0.f;
    for (int i = 0; i < per; i++) {
        float v = xr[threadIdx.x + (i << 8)];
        xv[i] = v; ss += v * v;
    }
    float tot = block_sum_256(ss);
    float scale = rsqrtf(tot / (float)cols + eps);
    for (int i = 0; i < per; i++) {
        int c = threadIdx.x + (i << 8);
        orow[c] = rna_tf32(xv[i] * scale * w[c]);
    }
}

// gated rmsnorm (tf32-rounded; feeds out-proj)
__global__ void gated_rmsnorm_kernel(const float* __restrict__ y, const float* __restrict__ zx,
                                     const float* __restrict__ w, float* __restrict__ out) {
    int row = blockIdx.x;
    const float* yr = y + (size_t)row * Ee;
    const float* zr = zx + (size_t)row * DIN;
    float* orow = out + (size_t)row * Ee;
    float g[8];
    float ss = 0.f;
#pragma unroll
    for (int i = 0; i < 8; i++) {
        int c = threadIdx.x + (i << 8);
        float v = yr[c] * silu_f(zr[c]);
        g[i] = v; ss += v * v;
    }
    float tot = block_sum_256(ss);
    float scale = rsqrtf(tot / (float)Ee + NEPS);
#pragma unroll
    for (int i = 0; i < 8; i++) {
        int c = threadIdx.x + (i << 8);
        orow[c] = rna_tf32(g[i] * scale * w[c]);
    }
}

// ---------------- conv + silu ----------------
__global__ void conv_silu_kernel(const float* __restrict__ zx,
                                 const float* __restrict__ wc,
                                 const float* __restrict__ bcv,
                                 float* __restrict__ xbc) {
    int idx = blockIdx.x * blockDim.x + threadIdx.x;
    if (idx >= TOK * CONVD) return;
    int t = idx / CONVD, c = idx - t * CONVD;
    int pos = t & (SEQL - 1);
    float s = bcv[c];
#pragma unroll
    for (int k = 0; k < Kc; k++) {
        int sp = pos - (Kc - 1) + k;
        if (sp >= 0)
            s += zx[(size_t)(t - (Kc - 1) + k) * DIN + Ee + c] * wc[c * Kc + k];
    }
    xbc[idx] = silu_f(s);
}

// ---------------- dt softplus ----------------
__global__ void dt_kernel(const float* __restrict__ zx, const float* __restrict__ dtb,
                          float* __restrict__ dt) {
    int idx = blockIdx.x * blockDim.x + threadIdx.x;
    if (idx >= TOK * NHh) return;
    int t = idx >> 5, h = idx & 31;
    float x = zx[(size_t)t * DIN + (Ee + CONVD) + h] + dtb[h];
    dt[idx] = (x > 20.f) ? x : log1pf(expf(x));
}

// ---------------- per-chunk cumsum of dA ----------------
__global__ void dacs_kernel(const float* __restrict__ dt, const float* __restrict__ alog,
                            float* __restrict__ acs) {
    int bc = blockIdx.x, h = blockIdx.y;
    int tb = ((bc >> 4) << 11) + ((bc & 15) << 7);
    int q = threadIdx.x;
    float a = -expf(alog[h]);
    float v = dt[(tb + q) * NHh + h] * a;
    int lane = q & 31;
#pragma unroll
    for (int o = 1; o < 32; o <<= 1) {
        float n = __shfl_up_sync(0xffffffffu, v, o);
        if (lane >= o) v += n;
    }
    __shared__ float ws[4];
    int wid = q >> 5;
    if (lane == 31) ws[wid] = v;
    __syncthreads();
    float add = 0.f;
    for (int w = 0; w < wid; w++) add += ws[w];
    acs[(bc * NHh + h) * Qq + q] = v + add;
}

// ---------------- per-chunk final states ----------------
__global__ __launch_bounds__(256) void chunk_states_kernel(
    const float* __restrict__ xbc, const float* __restrict__ dt,
    const float* __restrict__ acs, float* __restrict__ states) {
    int bc = blockIdx.x, h = blockIdx.y;
    int tb = ((bc >> 4) << 11) + ((bc & 15) << 7);
    __shared__ float w_s[128];
    __shared__ float xw[32 * 64];
    __shared__ float Bsm[32 * 128];
    int tid = threadIdx.x;
    const float* ac = acs + (bc * NHh + h) * Qq;
    if (tid < 128) {
        float last = ac[127];
        w_s[tid] = __expf(last - ac[tid]) * dt[(tb + tid) * NHh + h];
    }
    __syncthreads();
    int tp = tid >> 4, tn = tid & 15;
    float acc[4][8] = {};
    for (int qt = 0; qt < 128; qt += 32) {
        for (int i = tid; i < 2048; i += 256) {
            int qq = i >> 6, p = i & 63;
            xw[i] = xbc[(size_t)(tb + qt + qq) * CONVD + h * 64 + p] * w_s[qt + qq];
        }
        for (int i = tid; i < 4096; i += 256) {
            int qq = i >> 7, n = i & 127;
            Bsm[i] = xbc[(size_t)(tb + qt + qq) * CONVD + 2048 + n];
        }
        __syncthreads();
        for (int qq = 0; qq < 32; qq++) {
            float xv[4], bv[8];
#pragma unroll
            for (int i = 0; i < 4; i++) xv[i] = xw[qq * 64 + tp * 4 + i];
#pragma unroll
            for (int j = 0; j < 8; j++) bv[j] = Bsm[qq * 128 + tn * 8 + j];
#pragma unroll
            for (int i = 0; i < 4; i++)
#pragma unroll
                for (int j = 0; j < 8; j++) acc[i][j] += xv[i] * bv[j];
        }
        __syncthreads();
    }
    float* sp = states + (size_t)(bc * NHh + h) * 8192;
#pragma unroll
    for (int i = 0; i < 4; i++)
#pragma unroll
        for (int j = 0; j < 8; j++)
            sp[(tp * 4 + i) * 128 + tn * 8 + j] = acc[i][j];
}

// ---------------- inter-chunk recurrence ----------------
__global__ void chunk_scan_kernel(const float* __restrict__ states,
                                  const float* __restrict__ acs,
                                  float* __restrict__ prefix) {
    int b = blockIdx.x, h = blockIdx.y, tid = threadIdx.x;
    float run[32];
#pragma unroll
    for (int i = 0; i < 32; i++) run[i] = 0.f;
    for (int ch = 0; ch < 16; ch++) {
        int bc = b * 16 + ch;
        size_t base = (size_t)(bc * NHh + h) * 8192;
        float al = expf(acs[(bc * NHh + h) * Qq + 127]);
#pragma unroll
        for (int i = 0; i < 32; i++) {
            int e = (i << 8) + tid;
            prefix[base + e] = run[i];
            run[i] = run[i] * al + states[base + e];
        }
    }
}

// ---------------- CB ----------------
__global__ __launch_bounds__(256) void cb_kernel(const float* __restrict__ xbc,
                                                 float* __restrict__ cbout) {
    int bc = blockIdx.x;
    int tb = ((bc >> 4) << 11) + ((bc & 15) << 7);
    __shared__ float Ct[128][33];
    __shared__ float Bt[128][33];
    int tid = threadIdx.x;
    int tq = tid >> 4, ts = tid & 15;
    float acc[8][8] = {};
    for (int nt = 0; nt < 128; nt += 32) {
        for (int i = tid; i < 4096; i += 256) {
            int r = i >> 5, nn = i & 31;
            Ct[r][nn] = xbc[(size_t)(tb + r) * CONVD + 2176 + nt + nn];
            Bt[r][nn] = xbc[(size_t)(tb + r) * CONVD + 2048 + nt + nn];
        }
        __syncthreads();
        for (int nn = 0; nn < 32; nn++) {
            float ca[8], bb[8];
#pragma unroll
            for (int i = 0; i < 8; i++) ca[i] = Ct[tq * 8 + i][nn];
#pragma unroll
            for (int j = 0; j < 8; j++) bb[j] = Bt[ts * 8 + j][nn];
#pragma unroll
            for (int i = 0; i < 8; i++)
#pragma unroll
                for (int j = 0; j < 8; j++) acc[i][j] += ca[i] * bb[j];
        }
        __syncthreads();
    }
    float* o = cbout + (size_t)bc * 16384;
#pragma unroll
    for (int i = 0; i < 8; i++)
#pragma unroll
        for (int j = 0; j < 8; j++)
            o[(tq * 8 + i) * 128 + ts * 8 + j] = acc[i][j];
}

// ---------------- Y ----------------
__global__ __launch_bounds__(256) void y_kernel(
    const float* __restrict__ xbc, const float* __restrict__ dt,
    const float* __restrict__ acs, const float* __restrict__ prefix,
    const float* __restrict__ cb, const float* __restrict__ Dw,
    float* __restrict__ y) {
    int bc = blockIdx.x, h = blockIdx.y;
    int tb = ((bc >> 4) << 11) + ((bc & 15) << 7);
    __shared__ float acs_s[128], dts[128];
    __shared__ float pool[6336];
    int tid = threadIdx.x;
    if (tid < 128) {
        acs_s[tid] = acs[(bc * NHh + h) * Qq + tid];
        dts[tid] = dt[(tb + tid) * NHh + h];
    }
    __syncthreads();
    int q = tid >> 1, p0 = (tid & 1) << 5;
    float acc[32];
#pragma unroll
    for (int i = 0; i < 32; i++) acc[i] = 0.f;
    float aq = acs_s[q];

    float* xds = pool;
    float* CBs = pool + 2048;
    const float* cbb = cb + (size_t)bc * 16384;
    for (int st = 0; st < 128; st += 32) {
        for (int i = tid; i < 2048; i += 256) {
            int ss = i >> 6, p = i & 63;
            xds[i] = xbc[(size_t)(tb + st + ss) * CONVD + h * 64 + p] * dts[st + ss];
        }
        for (int i = tid; i < 4096; i += 256) {
            int qq = i >> 5, ss = i & 31;
            CBs[qq * 33 + ss] = cbb[qq * 128 + st + ss];
        }
        __syncthreads();
        int lim = q - st + 1;
        if (lim > 32) lim = 32;
        for (int ss = 0; ss < lim; ss++) {
            float m = CBs[q * 33 + ss] * __expf(aq - acs_s[st + ss]);
            const float* xr = xds + ss * 64 + p0;
#pragma unroll
            for (int i = 0; i < 32; i++) acc[i] += m * xr[i];
        }
        __syncthreads();
    }

    float eq = __expf(aq);
    float* Cs2 = pool;
    float* prefs = pool + 4224;
    const float* pref = prefix + (size_t)(bc * NHh + h) * 8192;
    for (int nt = 0; nt < 128; nt += 32) {
        for (int i = tid; i < 4096; i += 256) {
            int qq = i >> 5, nn = i & 31;
            Cs2[qq * 33 + nn] = xbc[(size_t)(tb + qq) * CONVD + 2176 + nt + nn];
        }
        for (int i = tid; i < 2048; i += 256) {
            int p = i >> 5, nn = i & 31;
            prefs[p * 33 + nn] = pref[p * 128 + nt + nn];
        }
        __syncthreads();
        for (int nn = 0; nn < 32; nn++) {
            float cv = Cs2[q * 33 + nn] * eq;
            const float* pr = prefs + p0 * 33 + nn;
#pragma unroll
            for (int i = 0; i < 32; i++) acc[i] += cv * pr[i * 33];
        }
        __syncthreads();
    }

    float Dh = Dw[h];
    int t = tb + q;
    const float* xr = xbc + (size_t)t * CONVD + h * 64 + p0;
    float* yo = y + (size_t)t * Ee + h * 64 + p0;
#pragma unroll
    for (int i = 0; i < 32; i++) yo[i] = acc[i] + Dh * xr[i];
}

// ---------------- host launcher ----------------
extern "C" void kernel_launch(void* const* d_in, const int* in_sizes, int n_in,
                              void* d_out, int out_size) {
    const float* hid   = (const float*)d_in[0];
    const float* wln1  = (const float*)d_in[1];
    const float* win   = (const float*)d_in[2];
    const float* wconv = (const float*)d_in[3];
    const float* bconv = (const float*)d_in[4];
    const float* dtb   = (const float*)d_in[5];
    const float* alog  = (const float*)d_in[6];
    const float* Dw    = (const float*)d_in[7];
    const float* wmn   = (const float*)d_in[8];
    const float* wout  = (const float*)d_in[9];
    const float* wln2  = (const float*)d_in[10];
    const float* wg    = (const float*)d_in[11];
    const float* wu    = (const float*)d_in[12];
    const float* wd    = (const float*)d_in[13];
    float* out = (float*)d_out;

    float *hnorm, *zx, *xbc, *dt, *acs, *states, *prefix, *cbp, *y, *y2, *hid2, *h2n, *gg, *gu;
    float *wr_in, *wr_out, *wr_g, *wr_u, *wr_d;
    cudaGetSymbolAddress((void**)&hnorm,  g_hnorm);
    cudaGetSymbolAddress((void**)&zx,     g_zx);
    cudaGetSymbolAddress((void**)&xbc,    g_xbc);
    cudaGetSymbolAddress((void**)&dt,     g_dt);
    cudaGetSymbolAddress((void**)&acs,    g_acs);
    cudaGetSymbolAddress((void**)&states, g_states);
    cudaGetSymbolAddress((void**)&prefix, g_prefix);
    cudaGetSymbolAddress((void**)&cbp,    g_cb);
    cudaGetSymbolAddress((void**)&y,      g_y);
    cudaGetSymbolAddress((void**)&y2,     g_y2);
    cudaGetSymbolAddress((void**)&hid2,   g_hid2);
    cudaGetSymbolAddress((void**)&h2n,    g_h2n);
    cudaGetSymbolAddress((void**)&gg,     g_gate);
    cudaGetSymbolAddress((void**)&gu,     g_up);
    cudaGetSymbolAddress((void**)&wr_in,  g_wr_in);
    cudaGetSymbolAddress((void**)&wr_out, g_wr_out);
    cudaGetSymbolAddress((void**)&wr_g,   g_wr_g);
    cudaGetSymbolAddress((void**)&wr_u,   g_wr_u);
    cudaGetSymbolAddress((void**)&wr_d,   g_wr_d);

    cudaFuncSetAttribute(mma_gemm<0>, cudaFuncAttributeMaxDynamicSharedMemorySize, GEMM_DSMEM);
    cudaFuncSetAttribute(mma_gemm<1>, cudaFuncAttributeMaxDynamicSharedMemorySize, GEMM_DSMEM);
    cudaFuncSetAttribute(mma_gemm<2>, cudaFuncAttributeMaxDynamicSharedMemorySize, GEMM_DSMEM);

    // round weights to tf32 (rna)
    round_tf32_kernel<<<(DIN * Hh + 255) / 256, 256>>>(win,  wr_in,  DIN * Hh);
    round_tf32_kernel<<<(Hh * Ee + 255) / 256, 256>>>(wout, wr_out, Hh * Ee);
    round_tf32_kernel<<<(FFd * Hh + 255) / 256, 256>>>(wg,   wr_g,   FFd * Hh);
    round_tf32_kernel<<<(FFd * Hh + 255) / 256, 256>>>(wu,   wr_u,   FFd * Hh);
    round_tf32_kernel<<<(Hh * FFd + 255) / 256, 256>>>(wd,   wr_d,   Hh * FFd);

    // 1) pre-norm
    rmsnorm_kernel<<<TOK, 256>>>(hid, wln1, hnorm, Hh, EPS1);
    // 2) in-projection
    mma_gemm<0><<<dim3((DIN + 127) / 128, TOK / 256), 256, GEMM_DSMEM>>>(hnorm, wr_in, nullptr, zx, TOK, DIN, Hh);
    // 3) conv + silu
    conv_silu_kernel<<<(TOK * CONVD + 255) / 256, 256>>>(zx, wconv, bconv, xbc);
    // 4) dt
    dt_kernel<<<(TOK * NHh + 255) / 256, 256>>>(zx, dtb, dt);
    // 5) cumsum
    dacs_kernel<<<dim3(NCHUNK, NHh), 128>>>(dt, alog, acs);
    // 6) chunk states
    chunk_states_kernel<<<dim3(NCHUNK, NHh), 256>>>(xbc, dt, acs, states);
    // 7) scan
    chunk_scan_kernel<<<dim3(2, NHh), 256>>>(states, acs, prefix);
    // 8) CB
    cb_kernel<<<NCHUNK, 256>>>(xbc, cbp);
    // 9) Y
    y_kernel<<<dim3(NCHUNK, NHh), 256>>>(xbc, dt, acs, prefix, cbp, Dw, y);
    // 10) gated norm
    gated_rmsnorm_kernel<<<TOK, 256>>>(y, zx, wmn, y2);
    // 11) out-proj + residual
    mma_gemm<1><<<dim3(Hh / 128, TOK / 256), 256, GEMM_DSMEM>>>(y2, wr_out, hid, hid2, TOK, Hh, Ee);
    // 12) norm 2
    rmsnorm_kernel<<<TOK, 256>>>(hid2, wln2, h2n, Hh, EPS1);
    // 13) gate projection
    mma_gemm<0><<<dim3(FFd / 128, TOK / 256), 256, GEMM_DSMEM>>>(h2n, wr_g, nullptr, gg, TOK, FFd, Hh);
    // 14) up projection with fused silu(gate)*up -> gu
    mma_gemm<2><<<dim3(FFd / 128, TOK / 256), 256, GEMM_DSMEM>>>(h2n, wr_u, gg, gu, TOK, FFd, Hh);
    // 16) down + residual
    mma_gemm<1><<<dim3(Hh / 128, TOK / 256), 256, GEMM_DSMEM>>>(gu, wr_d, hid2, out, TOK, Hh, FFd);
}

// round 5
// speedup vs baseline: 3.5029x; 1.2993x over previous
#include <cuda_runtime.h>
#include <cuda_fp16.h>
#include <cstdint>
#include <math.h>

// ---------------- problem dims ----------------
#define TOK   4096
#define SEQL  2048
#define Hh    1024
#define Ee    2048
#define NHh   32
#define Nn    128
#define Qq    128
#define Kc    4
#define CONVD 2304
#define DIN   4384
#define FFd   4096
#define NCHUNK 32
#define EPS1  1e-6f
#define NEPS  1e-5f

// ---------------- scratch ----------------
__device__ __half g_hnorm [TOK * Hh];
__device__ float  g_zx    [TOK * DIN];
__device__ float  g_xbc   [TOK * CONVD];
__device__ float  g_dt    [TOK * NHh];
__device__ float  g_acs   [NCHUNK * NHh * Qq];
__device__ float  g_states[NCHUNK * NHh * 64 * Nn];
__device__ float  g_prefix[NCHUNK * NHh * 64 * Nn];
__device__ float  g_cb    [NCHUNK * Qq * Qq];
__device__ float  g_y     [TOK * Ee];
__device__ __half g_y2    [TOK * Ee];
__device__ float  g_hid2  [TOK * Hh];
__device__ __half g_h2n   [TOK * Hh];
__device__ float  g_gate  [TOK * FFd];
__device__ __half g_gu    [TOK * FFd];
// fp16 weights
__device__ __half g_wh_in [DIN * Hh];
__device__ __half g_wh_out[Hh * Ee];
__device__ __half g_wh_g  [FFd * Hh];
__device__ __half g_wh_u  [FFd * Hh];
__device__ __half g_wh_d  [Hh * FFd];

// ---------------- helpers ----------------
__device__ __forceinline__ uint32_t smem_u32(const void* p) {
    return (uint32_t)__cvta_generic_to_shared(p);
}
__device__ __forceinline__ float silu_f(float x) { return x / (1.f + expf(-x)); }
__device__ __forceinline__ float block_sum_256(float v) {
    __shared__ float sh[8];
    __syncthreads();
    int lane = threadIdx.x & 31, wid = threadIdx.x >> 5;
#pragma unroll
    for (int o = 16; o > 0; o >>= 1) v += __shfl_down_sync(0xffffffffu, v, o);
    if (lane == 0) sh[wid] = v;
    __syncthreads();
    if (threadIdx.x == 0) {
        float s = 0.f;
#pragma unroll
        for (int i = 0; i < 8; i++) s += sh[i];
        sh[0] = s;
    }
    __syncthreads();
    return sh[0];
}
__device__ __forceinline__ void cp_async16(uint32_t dst, const void* src, int sz) {
    asm volatile("cp.async.cg.shared.global [%0], [%1], 16, %2;"
                 :: "r"(dst), "l"((unsigned long long)__cvta_generic_to_global(src)), "r"(sz)
                 : "memory");
}

// ---------------- fp16 mma.sync GEMM: C[M,N] = A[M,K] @ B[N,K]^T ----------------
// 256x128 CTA tile, BK=32, 4-stage cp.async, 256 threads.
// 8 warps 4(M)x2(N) -> 64x64 warp tile = 4(mt) x 8(nt) m16n8k16 MMAs x 2 ksteps.
// MODE: 0 = fp32 store, 1 = fp32 store + addsrc, 2 = half store of silu(aux)*acc
#define GSTAGES 4
#define LDSTH 40                                    // halves per smem row
#define STAGE_HALVES (384 * LDSTH)                  // 15360
#define GEMM_DSMEM (GSTAGES * STAGE_HALVES * 2)     // 122880 bytes

template<int MODE>
__global__ __launch_bounds__(256, 1) void mma_gemm(
    const __half* __restrict__ A, const __half* __restrict__ B,
    const float* __restrict__ aux, float* __restrict__ Cf, __half* __restrict__ Ch,
    int M, int N, int K)
{
    extern __shared__ __half smh[];
    int tid = threadIdx.x;
    int lane = tid & 31, wid = tid >> 5;
    int g = lane >> 2, tg = lane & 3;
    int wm = (wid >> 1) << 6;
    int wn = (wid & 1) << 6;
    int row0 = blockIdx.y << 8, col0 = blockIdx.x << 7;
    int NC = K >> 5;

    float acc[4][8][4];
#pragma unroll
    for (int i = 0; i < 4; i++)
#pragma unroll
        for (int j = 0; j < 8; j++)
#pragma unroll
            for (int k = 0; k < 4; k++) acc[i][j][k] = 0.f;

    auto load_stage = [&](int s, int c) {
        __half* As = smh + s * STAGE_HALVES;
        __half* Bs = As + 256 * LDSTH;
        const __half* Ag = A + (size_t)row0 * K + (c << 5);
        const __half* Bg = B + (size_t)col0 * K + (c << 5);
#pragma unroll
        for (int it = 0; it < 6; it++) {
            int i = tid + (it << 8);
            if (i < 1024) {
                int r = i >> 2, c8 = (i & 3) << 3;
                cp_async16(smem_u32(As + r * LDSTH + c8), Ag + (size_t)r * K + c8, 16);
            } else {
                int j = i - 1024;
                int r = j >> 2, c8 = (j & 3) << 3;
                int sz = (col0 + r < N) ? 16 : 0;
                cp_async16(smem_u32(Bs + r * LDSTH + c8), Bg + (size_t)r * K + c8, sz);
            }
        }
    };

#pragma unroll
    for (int s = 0; s < GSTAGES - 1; s++) {
        load_stage(s, s);
        asm volatile("cp.async.commit_group;" ::: "memory");
    }

    for (int c = 0; c < NC; c++) {
        asm volatile("cp.async.wait_group %0;" :: "n"(GSTAGES - 2) : "memory");
        __syncthreads();
        int nxt = c + GSTAGES - 1;
        if (nxt < NC) load_stage(nxt % GSTAGES, nxt);
        asm volatile("cp.async.commit_group;" ::: "memory");

        const __half* As = smh + (c % GSTAGES) * STAGE_HALVES;
        const __half* Bs = As + 256 * LDSTH;
#pragma unroll
        for (int ks = 0; ks < 2; ks++) {
            int k0 = ks << 4;
            uint32_t a[4][4], b[8][2];
#pragma unroll
            for (int mt = 0; mt < 4; mt++) {
                int r = wm + (mt << 4) + g;
                a[mt][0] = *(const uint32_t*)(As + r * LDSTH + k0 + 2 * tg);
                a[mt][1] = *(const uint32_t*)(As + (r + 8) * LDSTH + k0 + 2 * tg);
                a[mt][2] = *(const uint32_t*)(As + r * LDSTH + k0 + 8 + 2 * tg);
                a[mt][3] = *(const uint32_t*)(As + (r + 8) * LDSTH + k0 + 8 + 2 * tg);
            }
#pragma unroll
            for (int nt = 0; nt < 8; nt++) {
                int n = wn + (nt << 3) + g;
                b[nt][0] = *(const uint32_t*)(Bs + n * LDSTH + k0 + 2 * tg);
                b[nt][1] = *(const uint32_t*)(Bs + n * LDSTH + k0 + 8 + 2 * tg);
            }
#pragma unroll
            for (int mt = 0; mt < 4; mt++)
#pragma unroll
                for (int nt = 0; nt < 8; nt++) {
                    asm volatile(
                        "mma.sync.aligned.m16n8k16.row.col.f32.f16.f16.f32 "
                        "{%0,%1,%2,%3}, {%4,%5,%6,%7}, {%8,%9}, {%0,%1,%2,%3};"
                        : "+f"(acc[mt][nt][0]), "+f"(acc[mt][nt][1]),
                          "+f"(acc[mt][nt][2]), "+f"(acc[mt][nt][3])
                        : "r"(a[mt][0]), "r"(a[mt][1]), "r"(a[mt][2]), "r"(a[mt][3]),
                          "r"(b[nt][0]), "r"(b[nt][1]));
                }
        }
    }

    // epilogue
#pragma unroll
    for (int mt = 0; mt < 4; mt++) {
        int r = row0 + wm + (mt << 4) + g;
#pragma unroll
        for (int nt = 0; nt < 8; nt++) {
            int cc = col0 + wn + (nt << 3) + (tg << 1);
            if (cc >= N) continue;
            float v0 = acc[mt][nt][0], v1 = acc[mt][nt][1];
            float v2 = acc[mt][nt][2], v3 = acc[mt][nt][3];
            if (MODE == 1) {
                float2 s0 = *(const float2*)(aux + (size_t)r * N + cc);
                float2 s1 = *(const float2*)(aux + (size_t)(r + 8) * N + cc);
                v0 += s0.x; v1 += s0.y; v2 += s1.x; v3 += s1.y;
            }
            if (MODE == 2) {
                float2 g0 = *(const float2*)(aux + (size_t)r * N + cc);
                float2 g1 = *(const float2*)(aux + (size_t)(r + 8) * N + cc);
                __half2 h0 = __floats2half2_rn(silu_f(g0.x) * v0, silu_f(g0.y) * v1);
                __half2 h1 = __floats2half2_rn(silu_f(g1.x) * v2, silu_f(g1.y) * v3);
                *(__half2*)(Ch + (size_t)r * N + cc) = h0;
                *(__half2*)(Ch + (size_t)(r + 8) * N + cc) = h1;
            } else {
                *(float2*)(Cf + (size_t)r * N + cc) = make_float2(v0, v1);
                *(float2*)(Cf + (size_t)(r + 8) * N + cc) = make_float2(v2, v3);
            }
        }
    }
}

// ---------------- fp16 round copy (weights) ----------------
__global__ void round_h_kernel(const float* __restrict__ in, __half* __restrict__ out, int n) {
    int i = blockIdx.x * blockDim.x + threadIdx.x;
    if (i < n) out[i] = __float2half(in[i]);
}

// ---------------- rmsnorm (half output; feeds GEMM) ----------------
__global__ void rmsnorm_kernel(const float* __restrict__ x, const float* __restrict__ w,
                               __half* __restrict__ out, int cols, float eps) {
    int row = blockIdx.x;
    const float* xr = x + (size_t)row * cols;
    __half* orow = out + (size_t)row * cols;
    int per = cols >> 8;
    float xv[8];
    float ss = 0.f;
    for (int i = 0; i < per; i++) {
        float v = xr[threadIdx.x + (i << 8)];
        xv[i] = v; ss += v * v;
    }
    float tot = block_sum_256(ss);
    float scale = rsqrtf(tot / (float)cols + eps);
    for (int i = 0; i < per; i++) {
        int c = threadIdx.x + (i << 8);
        orow[c] = __float2half(xv[i] * scale * w[c]);
    }
}

// gated rmsnorm (half output; feeds out-proj)
__global__ void gated_rmsnorm_kernel(const float* __restrict__ y, const float* __restrict__ zx,
                                     const float* __restrict__ w, __half* __restrict__ out) {
    int row = blockIdx.x;
    const float* yr = y + (size_t)row * Ee;
    const float* zr = zx + (size_t)row * DIN;
    __half* orow = out + (size_t)row * Ee;
    float g[8];
    float ss = 0.f;
#pragma unroll
    for (int i = 0; i < 8; i++) {
        int c = threadIdx.x + (i << 8);
        float v = yr[c] * silu_f(zr[c]);
        g[i] = v; ss += v * v;
    }
    float tot = block_sum_256(ss);
    float scale = rsqrtf(tot / (float)Ee + NEPS);
#pragma unroll
    for (int i = 0; i < 8; i++) {
        int c = threadIdx.x + (i << 8);
        orow[c] = __float2half(g[i] * scale * w[c]);
    }
}

// ---------------- conv + silu ----------------
__global__ void conv_silu_kernel(const float* __restrict__ zx,
                                 const float* __restrict__ wc,
                                 const float* __restrict__ bcv,
                                 float* __restrict__ xbc) {
    int idx = blockIdx.x * blockDim.x + threadIdx.x;
    if (idx >= TOK * CONVD) return;
    int t = idx / CONVD, c = idx - t * CONVD;
    int pos = t & (SEQL - 1);
    float s = bcv[c];
#pragma unroll
    for (int k = 0; k < Kc; k++) {
        int sp = pos - (Kc - 1) + k;
        if (sp >= 0)
            s += zx[(size_t)(t - (Kc - 1) + k) * DIN + Ee + c] * wc[c * Kc + k];
    }
    xbc[idx] = silu_f(s);
}

// ---------------- dt softplus ----------------
__global__ void dt_kernel(const float* __restrict__ zx, const float* __restrict__ dtb,
                          float* __restrict__ dt) {
    int idx = blockIdx.x * blockDim.x + threadIdx.x;
    if (idx >= TOK * NHh) return;
    int t = idx >> 5, h = idx & 31;
    float x = zx[(size_t)t * DIN + (Ee + CONVD) + h] + dtb[h];
    dt[idx] = (x > 20.f) ? x : log1pf(expf(x));
}

// ---------------- per-chunk cumsum of dA ----------------
__global__ void dacs_kernel(const float* __restrict__ dt, const float* __restrict__ alog,
                            float* __restrict__ acs) {
    int bc = blockIdx.x, h = blockIdx.y;
    int tb = ((bc >> 4) << 11) + ((bc & 15) << 7);
    int q = threadIdx.x;
    float a = -expf(alog[h]);
    float v = dt[(tb + q) * NHh + h] * a;
    int lane = q & 31;
#pragma unroll
    for (int o = 1; o < 32; o <<= 1) {
        float n = __shfl_up_sync(0xffffffffu, v, o);
        if (lane >= o) v += n;
    }
    __shared__ float ws[4];
    int wid = q >> 5;
    if (lane == 31) ws[wid] = v;
    __syncthreads();
    float add = 0.f;
    for (int w = 0; w < wid; w++) add += ws[w];
    acs[(bc * NHh + h) * Qq + q] = v + add;
}

// ---------------- per-chunk final states ----------------
__global__ __launch_bounds__(256) void chunk_states_kernel(
    const float* __restrict__ xbc, const float* __restrict__ dt,
    const float* __restrict__ acs, float* __restrict__ states) {
    int bc = blockIdx.x, h = blockIdx.y;
    int tb = ((bc >> 4) << 11) + ((bc & 15) << 7);
    __shared__ float w_s[128];
    __shared__ float xw[32 * 64];
    __shared__ float Bsm[32 * 128];
    int tid = threadIdx.x;
    const float* ac = acs + (bc * NHh + h) * Qq;
    if (tid < 128) {
        float last = ac[127];
        w_s[tid] = __expf(last - ac[tid]) * dt[(tb + tid) * NHh + h];
    }
    __syncthreads();
    int tp = tid >> 4, tn = tid & 15;
    float acc[4][8] = {};
    for (int qt = 0; qt < 128; qt += 32) {
        for (int i = tid; i < 2048; i += 256) {
            int qq = i >> 6, p = i & 63;
            xw[i] = xbc[(size_t)(tb + qt + qq) * CONVD + h * 64 + p] * w_s[qt + qq];
        }
        for (int i = tid; i < 4096; i += 256) {
            int qq = i >> 7, n = i & 127;
            Bsm[i] = xbc[(size_t)(tb + qt + qq) * CONVD + 2048 + n];
        }
        __syncthreads();
        for (int qq = 0; qq < 32; qq++) {
            float xv[4], bv[8];
#pragma unroll
            for (int i = 0; i < 4; i++) xv[i] = xw[qq * 64 + tp * 4 + i];
#pragma unroll
            for (int j = 0; j < 8; j++) bv[j] = Bsm[qq * 128 + tn * 8 + j];
#pragma unroll
            for (int i = 0; i < 4; i++)
#pragma unroll
                for (int j = 0; j < 8; j++) acc[i][j] += xv[i] * bv[j];
        }
        __syncthreads();
    }
    float* sp = states + (size_t)(bc * NHh + h) * 8192;
#pragma unroll
    for (int i = 0; i < 4; i++)
#pragma unroll
        for (int j = 0; j < 8; j++)
            sp[(tp * 4 + i) * 128 + tn * 8 + j] = acc[i][j];
}

// ---------------- inter-chunk recurrence ----------------
__global__ void chunk_scan_kernel(const float* __restrict__ states,
                                  const float* __restrict__ acs,
                                  float* __restrict__ prefix) {
    int b = blockIdx.x, h = blockIdx.y, tid = threadIdx.x;
    float run[32];
#pragma unroll
    for (int i = 0; i < 32; i++) run[i] = 0.f;
    for (int ch = 0; ch < 16; ch++) {
        int bc = b * 16 + ch;
        size_t base = (size_t)(bc * NHh + h) * 8192;
        float al = expf(acs[(bc * NHh + h) * Qq + 127]);
#pragma unroll
        for (int i = 0; i < 32; i++) {
            int e = (i << 8) + tid;
            prefix[base + e] = run[i];
            run[i] = run[i] * al + states[base + e];
        }
    }
}

// ---------------- CB ----------------
__global__ __launch_bounds__(256) void cb_kernel(const float* __restrict__ xbc,
                                                 float* __restrict__ cbout) {
    int bc = blockIdx.x;
    int tb = ((bc >> 4) << 11) + ((bc & 15) << 7);
    __shared__ float Ct[128][33];
    __shared__ float Bt[128][33];
    int tid = threadIdx.x;
    int tq = tid >> 4, ts = tid & 15;
    float acc[8][8] = {};
    for (int nt = 0; nt < 128; nt += 32) {
        for (int i = tid; i < 4096; i += 256) {
            int r = i >> 5, nn = i & 31;
            Ct[r][nn] = xbc[(size_t)(tb + r) * CONVD + 2176 + nt + nn];
            Bt[r][nn] = xbc[(size_t)(tb + r) * CONVD + 2048 + nt + nn];
        }
        __syncthreads();
        for (int nn = 0; nn < 32; nn++) {
            float ca[8], bb[8];
#pragma unroll
            for (int i = 0; i < 8; i++) ca[i] = Ct[tq * 8 + i][nn];
#pragma unroll
            for (int j = 0; j < 8; j++) bb[j] = Bt[ts * 8 + j][nn];
#pragma unroll
            for (int i = 0; i < 8; i++)
#pragma unroll
                for (int j = 0; j < 8; j++) acc[i][j] += ca[i] * bb[j];
        }
        __syncthreads();
    }
    float* o = cbout + (size_t)bc * 16384;
#pragma unroll
    for (int i = 0; i < 8; i++)
#pragma unroll
        for (int j = 0; j < 8; j++)
            o[(tq * 8 + i) * 128 + ts * 8 + j] = acc[i][j];
}

// ---------------- Y ----------------
__global__ __launch_bounds__(256) void y_kernel(
    const float* __restrict__ xbc, const float* __restrict__ dt,
    const float* __restrict__ acs, const float* __restrict__ prefix,
    const float* __restrict__ cb, const float* __restrict__ Dw,
    float* __restrict__ y) {
    int bc = blockIdx.x, h = blockIdx.y;
    int tb = ((bc >> 4) << 11) + ((bc & 15) << 7);
    __shared__ float acs_s[128], dts[128];
    __shared__ float pool[6336];
    int tid = threadIdx.x;
    if (tid < 128) {
        acs_s[tid] = acs[(bc * NHh + h) * Qq + tid];
        dts[tid] = dt[(tb + tid) * NHh + h];
    }
    __syncthreads();
    int q = tid >> 1, p0 = (tid & 1) << 5;
    float acc[32];
#pragma unroll
    for (int i = 0; i < 32; i++) acc[i] = 0.f;
    float aq = acs_s[q];

    float* xds = pool;
    float* CBs = pool + 2048;
    const float* cbb = cb + (size_t)bc * 16384;
    for (int st = 0; st < 128; st += 32) {
        for (int i = tid; i < 2048; i += 256) {
            int ss = i >> 6, p = i & 63;
            xds[i] = xbc[(size_t)(tb + st + ss) * CONVD + h * 64 + p] * dts[st + ss];
        }
        for (int i = tid; i < 4096; i += 256) {
            int qq = i >> 5, ss = i & 31;
            CBs[qq * 33 + ss] = cbb[qq * 128 + st + ss];
        }
        __syncthreads();
        int lim = q - st + 1;
        if (lim > 32) lim = 32;
        for (int ss = 0; ss < lim; ss++) {
            float m = CBs[q * 33 + ss] * __expf(aq - acs_s[st + ss]);
            const float* xr = xds + ss * 64 + p0;
#pragma unroll
            for (int i = 0; i < 32; i++) acc[i] += m * xr[i];
        }
        __syncthreads();
    }

    float eq = __expf(aq);
    float* Cs2 = pool;
    float* prefs = pool + 4224;
    const float* pref = prefix + (size_t)(bc * NHh + h) * 8192;
    for (int nt = 0; nt < 128; nt += 32) {
        for (int i = tid; i < 4096; i += 256) {
            int qq = i >> 5, nn = i & 31;
            Cs2[qq * 33 + nn] = xbc[(size_t)(tb + qq) * CONVD + 2176 + nt + nn];
        }
        for (int i = tid; i < 2048; i += 256) {
            int p = i >> 5, nn = i & 31;
            prefs[p * 33 + nn] = pref[p * 128 + nt + nn];
        }
        __syncthreads();
        for (int nn = 0; nn < 32; nn++) {
            float cv = Cs2[q * 33 + nn] * eq;
            const float* pr = prefs + p0 * 33 + nn;
#pragma unroll
            for (int i = 0; i < 32; i++) acc[i] += cv * pr[i * 33];
        }
        __syncthreads();
    }

    float Dh = Dw[h];
    int t = tb + q;
    const float* xr = xbc + (size_t)t * CONVD + h * 64 + p0;
    float* yo = y + (size_t)t * Ee + h * 64 + p0;
#pragma unroll
    for (int i = 0; i < 32; i++) yo[i] = acc[i] + Dh * xr[i];
}

// ---------------- host launcher ----------------
extern "C" void kernel_launch(void* const* d_in, const int* in_sizes, int n_in,
                              void* d_out, int out_size) {
    const float* hid   = (const float*)d_in[0];
    const float* wln1  = (const float*)d_in[1];
    const float* win   = (const float*)d_in[2];
    const float* wconv = (const float*)d_in[3];
    const float* bconv = (const float*)d_in[4];
    const float* dtb   = (const float*)d_in[5];
    const float* alog  = (const float*)d_in[6];
    const float* Dw    = (const float*)d_in[7];
    const float* wmn   = (const float*)d_in[8];
    const float* wout  = (const float*)d_in[9];
    const float* wln2  = (const float*)d_in[10];
    const float* wg    = (const float*)d_in[11];
    const float* wu    = (const float*)d_in[12];
    const float* wd    = (const float*)d_in[13];
    float* out = (float*)d_out;

    __half *hnorm, *y2, *h2n, *gu, *wh_in, *wh_out, *wh_g, *wh_u, *wh_d;
    float *zx, *xbc, *dt, *acs, *states, *prefix, *cbp, *y, *hid2, *gg;
    cudaGetSymbolAddress((void**)&hnorm,  g_hnorm);
    cudaGetSymbolAddress((void**)&zx,     g_zx);
    cudaGetSymbolAddress((void**)&xbc,    g_xbc);
    cudaGetSymbolAddress((void**)&dt,     g_dt);
    cudaGetSymbolAddress((void**)&acs,    g_acs);
    cudaGetSymbolAddress((void**)&states, g_states);
    cudaGetSymbolAddress((void**)&prefix, g_prefix);
    cudaGetSymbolAddress((void**)&cbp,    g_cb);
    cudaGetSymbolAddress((void**)&y,      g_y);
    cudaGetSymbolAddress((void**)&y2,     g_y2);
    cudaGetSymbolAddress((void**)&hid2,   g_hid2);
    cudaGetSymbolAddress((void**)&h2n,    g_h2n);
    cudaGetSymbolAddress((void**)&gg,     g_gate);
    cudaGetSymbolAddress((void**)&gu,     g_gu);
    cudaGetSymbolAddress((void**)&wh_in,  g_wh_in);
    cudaGetSymbolAddress((void**)&wh_out, g_wh_out);
    cudaGetSymbolAddress((void**)&wh_g,   g_wh_g);
    cudaGetSymbolAddress((void**)&wh_u,   g_wh_u);
    cudaGetSymbolAddress((void**)&wh_d,   g_wh_d);

    cudaFuncSetAttribute(mma_gemm<0>, cudaFuncAttributeMaxDynamicSharedMemorySize, GEMM_DSMEM);
    cudaFuncSetAttribute(mma_gemm<1>, cudaFuncAttributeMaxDynamicSharedMemorySize, GEMM_DSMEM);
    cudaFuncSetAttribute(mma_gemm<2>, cudaFuncAttributeMaxDynamicSharedMemorySize, GEMM_DSMEM);

    // weights -> fp16
    round_h_kernel<<<(DIN * Hh + 255) / 256, 256>>>(win,  wh_in,  DIN * Hh);
    round_h_kernel<<<(Hh * Ee + 255) / 256, 256>>>(wout, wh_out, Hh * Ee);
    round_h_kernel<<<(FFd * Hh + 255) / 256, 256>>>(wg,   wh_g,   FFd * Hh);
    round_h_kernel<<<(FFd * Hh + 255) / 256, 256>>>(wu,   wh_u,   FFd * Hh);
    round_h_kernel<<<(Hh * FFd + 255) / 256, 256>>>(wd,   wh_d,   Hh * FFd);

    // 1) pre-norm (half out)
    rmsnorm_kernel<<<TOK, 256>>>(hid, wln1, hnorm, Hh, EPS1);
    // 2) in-projection
    mma_gemm<0><<<dim3((DIN + 127) / 128, TOK / 256), 256, GEMM_DSMEM>>>(hnorm, wh_in, nullptr, zx, nullptr, TOK, DIN, Hh);
    // 3) conv + silu
    conv_silu_kernel<<<(TOK * CONVD + 255) / 256, 256>>>(zx, wconv, bconv, xbc);
    // 4) dt
    dt_kernel<<<(TOK * NHh + 255) / 256, 256>>>(zx, dtb, dt);
    // 5) cumsum
    dacs_kernel<<<dim3(NCHUNK, NHh), 128>>>(dt, alog, acs);
    // 6) chunk states
    chunk_states_kernel<<<dim3(NCHUNK, NHh), 256>>>(xbc, dt, acs, states);
    // 7) scan
    chunk_scan_kernel<<<dim3(2, NHh), 256>>>(states, acs, prefix);
    // 8) CB
    cb_kernel<<<NCHUNK, 256>>>(xbc, cbp);
    // 9) Y
    y_kernel<<<dim3(NCHUNK, NHh), 256>>>(xbc, dt, acs, prefix, cbp, Dw, y);
    // 10) gated norm (half out)
    gated_rmsnorm_kernel<<<TOK, 256>>>(y, zx, wmn, y2);
    // 11) out-proj + residual (fp32 out)
    mma_gemm<1><<<dim3(Hh / 128, TOK / 256), 256, GEMM_DSMEM>>>(y2, wh_out, hid, hid2, nullptr, TOK, Hh, Ee);
    // 12) norm 2 (half out)
    rmsnorm_kernel<<<TOK, 256>>>(hid2, wln2, h2n, Hh, EPS1);
    // 13) gate projection (fp32 out)
    mma_gemm<0><<<dim3(FFd / 128, TOK / 256), 256, GEMM_DSMEM>>>(h2n, wh_g, nullptr, gg, nullptr, TOK, FFd, Hh);
    // 14) up projection + fused silu(gate)*up (half out)
    mma_gemm<2><<<dim3(FFd / 128, TOK / 256), 256, GEMM_DSMEM>>>(h2n, wh_u, gg, nullptr, gu, TOK, FFd, Hh);
    // 16) down + residual -> output
    mma_gemm<1><<<dim3(Hh / 128, TOK / 256), 256, GEMM_DSMEM>>>(gu, wh_d, hid2, out, nullptr, TOK, Hh, FFd);
}